// round 2
// baseline (speedup 1.0000x reference)
#include <cuda_runtime.h>
#include <math.h>

#define BB   4
#define SS   1024
#define DD   512
#define HH   8
#define CC   64
#define MLPD 2048
#define LL   4
#define TOPKK 256
#define D3   (3*DD)

// ---------------- scratch (static device globals; no dynamic allocation) ----
__device__ float g_x  [BB*SS*DD];                  // residual stream
__device__ float g_ln [BB*SS*DD];                  // layernorm output
__device__ float g_qkv[(size_t)BB*D3*SS];          // (B, 3D, S)
__device__ float g_q  [BB*HH*SS*CC];               // (B,H,S,C) normalized
__device__ float g_k  [BB*HH*SS*CC];
__device__ float g_v  [BB*HH*SS*CC];
__device__ float g_sc [(size_t)BB*HH*SS*SS];       // scores / probs (B,H,S,S)
__device__ float g_ao [BB*HH*SS*CC];               // attn out (B,H,S,C)
__device__ float g_aop[BB*SS*DD];                  // attn out (B,S,D)
__device__ float g_mlp[(size_t)BB*SS*MLPD];        // mlp hidden

// ---------------- helpers ----------------
__device__ __forceinline__ float geluf(float x) {
    return 0.5f * x * (1.0f + erff(x * 0.70710678118654752440f));
}
__device__ __forceinline__ unsigned f2key(float f) {
    unsigned u = __float_as_uint(f);
    return (u & 0x80000000u) ? ~u : (u | 0x80000000u);
}
__device__ __forceinline__ float key2f(unsigned k) {
    unsigned u = (k & 0x80000000u) ? (k & 0x7FFFFFFFu) : ~k;
    return __uint_as_float(u);
}

// ---------------- x = x_in + pos (broadcast over batch) ----------------
__global__ void add_pos_kernel(const float* __restrict__ x,
                               const float* __restrict__ pos,
                               float* __restrict__ out, int total, int per_b) {
    int i = blockIdx.x * blockDim.x + threadIdx.x;
    if (i < total) out[i] = x[i] + pos[i % per_b];
}

// ---------------- layernorm over D=512, one block (128 thr) per row ---------
__global__ void ln_kernel(const float* __restrict__ in,
                          const float* __restrict__ w,
                          const float* __restrict__ b,
                          float* __restrict__ out) {
    int row = blockIdx.x;
    const float* xr = in + (size_t)row * DD;
    float* yr = out + (size_t)row * DD;
    int tid = threadIdx.x;            // 128 threads
    float v[4], s = 0.f, sq = 0.f;
#pragma unroll
    for (int i = 0; i < 4; i++) {
        v[i] = xr[tid + i * 128];
        s += v[i]; sq += v[i] * v[i];
    }
    __shared__ float rs[32], rq[32];
#pragma unroll
    for (int o = 16; o; o >>= 1) {
        s  += __shfl_down_sync(0xFFFFFFFFu, s,  o);
        sq += __shfl_down_sync(0xFFFFFFFFu, sq, o);
    }
    int warp = tid >> 5, lane = tid & 31;
    if (lane == 0) { rs[warp] = s; rq[warp] = sq; }
    __syncthreads();
    if (tid == 0) {
        float a = 0.f, c = 0.f;
        for (int i = 0; i < 4; i++) { a += rs[i]; c += rq[i]; }
        rs[0] = a; rq[0] = c;
    }
    __syncthreads();
    float mu   = rs[0] * (1.0f / DD);
    float var  = rq[0] * (1.0f / DD) - mu * mu;
    float rstd = rsqrtf(var + 1e-6f);
#pragma unroll
    for (int i = 0; i < 4; i++) {
        int d = tid + i * 128;
        yr[d] = (v[i] - mu) * rstd * w[d] + b[d];
    }
}

// ---------------- generic GEMM: Y = act(X·W^T + bias) [+=] ------------------
// X: (N,K) row-major, W: (M,K) row-major. 64x64 tile, BK=16, 256 thr, 4x4/thr.
// TRANS_OUT: Y[m*N+n]  else Y[n*M+m]. Batched via blockIdx.z strides.
template <bool TRANS_OUT, bool GELU_ACT, bool RESID>
__global__ void gemm_xwt(const float* __restrict__ Xb,
                         const float* __restrict__ Wb,
                         const float* __restrict__ bias,
                         float* __restrict__ Yb,
                         int N, int M, int K,
                         long xs, long ws, long ys) {
    const float* X = Xb + (size_t)blockIdx.z * xs;
    const float* W = Wb + (size_t)blockIdx.z * ws;
    float* Y = Yb + (size_t)blockIdx.z * ys;
    __shared__ float Xs[16][64];
    __shared__ float Wsm[16][64];
    int m0 = blockIdx.x * 64, n0 = blockIdx.y * 64;
    int tid = threadIdx.x;
    int tr = tid >> 4, tc = tid & 15;
    int lrow = tid >> 2;
    int lk = (tid & 3) * 4;
    float acc[4][4];
#pragma unroll
    for (int i = 0; i < 4; i++)
#pragma unroll
        for (int j = 0; j < 4; j++) acc[i][j] = 0.f;

    const float* xp = X + (size_t)(n0 + lrow) * K + lk;
    const float* wp = W + (size_t)(m0 + lrow) * K + lk;

    for (int k0 = 0; k0 < K; k0 += 16) {
        float4 xa = *(const float4*)(xp + k0);
        float4 wa = *(const float4*)(wp + k0);
        Xs[lk + 0][lrow] = xa.x; Xs[lk + 1][lrow] = xa.y;
        Xs[lk + 2][lrow] = xa.z; Xs[lk + 3][lrow] = xa.w;
        Wsm[lk + 0][lrow] = wa.x; Wsm[lk + 1][lrow] = wa.y;
        Wsm[lk + 2][lrow] = wa.z; Wsm[lk + 3][lrow] = wa.w;
        __syncthreads();
#pragma unroll
        for (int kk = 0; kk < 16; kk++) {
            float4 a  = *(const float4*)&Xs[kk][tr * 4];
            float4 b4 = *(const float4*)&Wsm[kk][tc * 4];
            acc[0][0] += a.x * b4.x; acc[0][1] += a.x * b4.y;
            acc[0][2] += a.x * b4.z; acc[0][3] += a.x * b4.w;
            acc[1][0] += a.y * b4.x; acc[1][1] += a.y * b4.y;
            acc[1][2] += a.y * b4.z; acc[1][3] += a.y * b4.w;
            acc[2][0] += a.z * b4.x; acc[2][1] += a.z * b4.y;
            acc[2][2] += a.z * b4.z; acc[2][3] += a.z * b4.w;
            acc[3][0] += a.w * b4.x; acc[3][1] += a.w * b4.y;
            acc[3][2] += a.w * b4.z; acc[3][3] += a.w * b4.w;
        }
        __syncthreads();
    }
#pragma unroll
    for (int j = 0; j < 4; j++) {
        int m = m0 + tc * 4 + j;
        float bj = bias ? bias[m] : 0.f;
#pragma unroll
        for (int i = 0; i < 4; i++) {
            int n = n0 + tr * 4 + i;
            float v = acc[i][j] + bj;
            if (GELU_ACT) v = geluf(v);
            size_t idx = TRANS_OUT ? ((size_t)m * N + n) : ((size_t)n * M + m);
            if (RESID) Y[idx] += v; else Y[idx] = v;
        }
    }
}

// ---------------- attn·V : Y[n,m] = sum_k P[n,k] * V[k,m]  (V K-major) ------
// per batch bh: P (S,S), V (S,C=64), Y (S,C). M=64 so grid.x = 1.
__global__ void gemm_attnv(const float* __restrict__ Pb,
                           const float* __restrict__ Vb,
                           float* __restrict__ Yb) {
    int z = blockIdx.z;
    const float* P = Pb + (size_t)z * SS * SS;
    const float* V = Vb + (size_t)z * SS * CC;
    float* Y = Yb + (size_t)z * SS * CC;
    __shared__ float Xs[16][64];
    __shared__ float Wsm[16][64];
    int n0 = blockIdx.y * 64;
    int tid = threadIdx.x;
    int tr = tid >> 4, tc = tid & 15;
    int lrow = tid >> 2;
    int lk = (tid & 3) * 4;
    int wkk = tid >> 4;            // 0..15
    int wm  = (tid & 15) * 4;      // 0..60
    float acc[4][4];
#pragma unroll
    for (int i = 0; i < 4; i++)
#pragma unroll
        for (int j = 0; j < 4; j++) acc[i][j] = 0.f;

    const float* xp = P + (size_t)(n0 + lrow) * SS + lk;
    for (int k0 = 0; k0 < SS; k0 += 16) {
        float4 xa = *(const float4*)(xp + k0);
        Xs[lk + 0][lrow] = xa.x; Xs[lk + 1][lrow] = xa.y;
        Xs[lk + 2][lrow] = xa.z; Xs[lk + 3][lrow] = xa.w;
        float4 wa = *(const float4*)(V + (size_t)(k0 + wkk) * CC + wm);
        *(float4*)&Wsm[wkk][wm] = wa;
        __syncthreads();
#pragma unroll
        for (int kk = 0; kk < 16; kk++) {
            float4 a  = *(const float4*)&Xs[kk][tr * 4];
            float4 b4 = *(const float4*)&Wsm[kk][tc * 4];
            acc[0][0] += a.x * b4.x; acc[0][1] += a.x * b4.y;
            acc[0][2] += a.x * b4.z; acc[0][3] += a.x * b4.w;
            acc[1][0] += a.y * b4.x; acc[1][1] += a.y * b4.y;
            acc[1][2] += a.y * b4.z; acc[1][3] += a.y * b4.w;
            acc[2][0] += a.z * b4.x; acc[2][1] += a.z * b4.y;
            acc[2][2] += a.z * b4.z; acc[2][3] += a.z * b4.w;
            acc[3][0] += a.w * b4.x; acc[3][1] += a.w * b4.y;
            acc[3][2] += a.w * b4.z; acc[3][3] += a.w * b4.w;
        }
        __syncthreads();
    }
#pragma unroll
    for (int i = 0; i < 4; i++) {
        int n = n0 + tr * 4 + i;
#pragma unroll
        for (int j = 0; j < 4; j++)
            Y[(size_t)n * CC + tc * 4 + j] = acc[i][j];
    }
}

// ------- depthwise conv3 + head split + (q,k) L2-normalize ----------------
// grid: (S/64, 3*H, B). block 256. q/k/v outputs in (B,H,S,C).
__global__ void conv_heads(const float* __restrict__ qkv,
                           const float* __restrict__ dw,  // (3D, 3)
                           float* __restrict__ q,
                           float* __restrict__ k,
                           float* __restrict__ v) {
    int b = blockIdx.z;
    int part = blockIdx.y / HH, h = blockIdx.y % HH;
    int s0 = blockIdx.x * 64;
    int ch0 = part * DD + h * CC;
    __shared__ float tin[64][66];
    __shared__ float ct[64][65];
    int tid = threadIdx.x;

    for (int idx = tid; idx < 64 * 66; idx += 256) {
        int c = idx / 66, j = idx % 66;
        int s = s0 + j - 1;
        float val = 0.f;
        if (s >= 0 && s < SS) val = qkv[((size_t)b * D3 + ch0 + c) * SS + s];
        tin[c][j] = val;
    }
    __syncthreads();
    for (int idx = tid; idx < 4096; idx += 256) {
        int c = idx >> 6, s = idx & 63;
        const float* wp = dw + (ch0 + c) * 3;
        ct[c][s] = wp[0] * tin[c][s] + wp[1] * tin[c][s + 1] + wp[2] * tin[c][s + 2];
    }
    __syncthreads();
    float* out = (part == 0 ? q : (part == 1 ? k : v));
    out += ((size_t)(b * HH + h) * SS + s0) * CC;
    if (part == 2) {
        for (int idx = tid; idx < 4096; idx += 256) {
            int s = idx >> 6, c = idx & 63;
            out[s * CC + c] = ct[c][s];
        }
    } else {
        __shared__ float red[4][64];
        __shared__ float rnorm[64];
        int tx = tid & 63, ty = tid >> 6;
        float p = 0.f;
        for (int c = ty * 16; c < ty * 16 + 16; c++) {
            float u = ct[c][tx];
            p += u * u;
        }
        red[ty][tx] = p;
        __syncthreads();
        if (ty == 0) {
            float nn = red[0][tx] + red[1][tx] + red[2][tx] + red[3][tx];
            rnorm[tx] = 1.f / fmaxf(sqrtf(nn), 1e-12f);
        }
        __syncthreads();
        for (int idx = tid; idx < 4096; idx += 256) {
            int s = idx >> 6, c = idx & 63;
            out[s * CC + c] = ct[c][s] * rnorm[s];
        }
    }
}

// ------- top-k (exact radix select on float keys) + masked softmax ---------
// grid: (S, B*H), block 256. In-place on scores row (scaled by temp[h]).
__global__ void topk_softmax(float* __restrict__ scores,
                             const float* __restrict__ temp) {
    int bh = blockIdx.y;
    int h = bh % HH;
    int s = blockIdx.x;
    float* row = scores + ((size_t)bh * SS + s) * SS;
    float t = temp[h];
    __shared__ unsigned keys[SS];
    __shared__ unsigned hist[256];
    __shared__ float fred[256];
    __shared__ unsigned sh_prefix;
    __shared__ int sh_k;
    int tid = threadIdx.x;

    float lmax = -3.4e38f;
#pragma unroll
    for (int i = 0; i < 4; i++) {
        int idx = tid + i * 256;
        float f = row[idx] * t;
        keys[idx] = f2key(f);
        lmax = fmaxf(lmax, f);
    }
    fred[tid] = lmax;
    __syncthreads();
    for (int o = 128; o; o >>= 1) {
        if (tid < o) fred[tid] = fmaxf(fred[tid], fred[tid + o]);
        __syncthreads();
    }
    float maxv = fred[0];
    if (tid == 0) { sh_prefix = 0u; sh_k = TOPKK; }
    __syncthreads();

    for (int pass = 0; pass < 4; pass++) {
        int shift = 24 - 8 * pass;
        hist[tid] = 0u;
        if (tid < 0) {} // (256 threads == 256 bins)
        __syncthreads();
        unsigned pref = sh_prefix;
        unsigned mask = (pass == 0) ? 0u : (0xFFFFFFFFu << (shift + 8));
#pragma unroll
        for (int i = 0; i < 4; i++) {
            unsigned key = keys[tid + i * 256];
            if ((key & mask) == pref) atomicAdd(&hist[(key >> shift) & 255], 1u);
        }
        __syncthreads();
        if (tid == 0) {
            int kk = sh_k;
            int d = 255;
            for (; d > 0; d--) {
                int c = (int)hist[d];
                if (kk <= c) break;
                kk -= c;
            }
            sh_k = kk;
            sh_prefix = pref | ((unsigned)d << shift);
        }
        __syncthreads();
    }
    float vstar = key2f(sh_prefix);
    float m = fminf(fmaxf(maxv, -10000.f), 10000.f);

    float lsum = 0.f;
#pragma unroll
    for (int i = 0; i < 4; i++) {
        int idx = tid + i * 256;
        float f = key2f(keys[idx]);
        float p = (f >= vstar) ? fminf(fmaxf(f, -10000.f), 10000.f) : -10000.f;
        float e = expf(p - m);
        ((float*)keys)[idx] = e;   // each thread rewrites its own slots only
        lsum += e;
    }
    fred[tid] = lsum;
    __syncthreads();
    for (int o = 128; o; o >>= 1) {
        if (tid < o) fred[tid] += fred[tid + o];
        __syncthreads();
    }
    float inv = 1.f / fred[0];
#pragma unroll
    for (int i = 0; i < 4; i++) {
        int idx = tid + i * 256;
        row[idx] = ((float*)keys)[idx] * inv;
    }
}

// ------- (B,H,S,C) -> (B,S,D) ----------------------------------------------
__global__ void permute_ao(const float* __restrict__ ao, float* __restrict__ out) {
    int idx = blockIdx.x * 256 + threadIdx.x;
    int d = idx % DD;
    int bs = idx / DD;
    int si = bs % SS, b = bs / SS;
    int h = d / CC, c = d % CC;
    out[idx] = ao[(((size_t)(b * HH + h)) * SS + si) * CC + c];
}

// ---------------- host orchestration ----------------------------------------
extern "C" void kernel_launch(void* const* d_in, const int* in_sizes, int n_in,
                              void* d_out, int out_size) {
    (void)in_sizes; (void)n_in; (void)out_size;
    const float* x      = (const float*)d_in[0];
    const float* pos    = (const float*)d_in[1];
    const float* ln1_w  = (const float*)d_in[2];
    const float* ln1_b  = (const float*)d_in[3];
    const float* qkv_w  = (const float*)d_in[4];
    const float* dw_w   = (const float*)d_in[5];
    const float* temp   = (const float*)d_in[6];
    const float* proj_w = (const float*)d_in[7];
    const float* ln2_w  = (const float*)d_in[8];
    const float* ln2_b  = (const float*)d_in[9];
    const float* mlp_w1 = (const float*)d_in[10];
    const float* mlp_b1 = (const float*)d_in[11];
    const float* mlp_w2 = (const float*)d_in[12];
    const float* mlp_b2 = (const float*)d_in[13];
    const float* lnf_w  = (const float*)d_in[14];
    const float* lnf_b  = (const float*)d_in[15];
    float* out = (float*)d_out;

    float *gx, *gln, *gqkv, *gq, *gk, *gv, *gsc, *gao, *gaop, *gmlp;
    cudaGetSymbolAddress((void**)&gx,   g_x);
    cudaGetSymbolAddress((void**)&gln,  g_ln);
    cudaGetSymbolAddress((void**)&gqkv, g_qkv);
    cudaGetSymbolAddress((void**)&gq,   g_q);
    cudaGetSymbolAddress((void**)&gk,   g_k);
    cudaGetSymbolAddress((void**)&gv,   g_v);
    cudaGetSymbolAddress((void**)&gsc,  g_sc);
    cudaGetSymbolAddress((void**)&gao,  g_ao);
    cudaGetSymbolAddress((void**)&gaop, g_aop);
    cudaGetSymbolAddress((void**)&gmlp, g_mlp);

    const int NBS = BB * SS;           // 4096 rows
    add_pos_kernel<<<(BB * SS * DD + 255) / 256, 256>>>(x, pos, gx, BB * SS * DD, SS * DD);

    for (int l = 0; l < LL; l++) {
        // ln1
        ln_kernel<<<NBS, 128>>>(gx, ln1_w + l * DD, ln1_b + l * DD, gln);
        // qkv 1x1 conv: per batch, (1536 x 512) x (512 x 1024) -> (B, 3D, S)
        gemm_xwt<true, false, false><<<dim3(D3 / 64, SS / 64, BB), 256>>>(
            gln, qkv_w + (size_t)l * D3 * DD, nullptr, gqkv,
            SS, D3, DD, (long)SS * DD, 0, (long)D3 * SS);
        // depthwise conv3 + head split + q/k normalize
        conv_heads<<<dim3(SS / 64, 3 * HH, BB), 256>>>(
            gqkv, dw_w + (size_t)l * D3 * 3, gq, gk, gv);
        // scores = q k^T  (batched over B*H, K = 64)
        gemm_xwt<false, false, false><<<dim3(SS / 64, SS / 64, BB * HH), 256>>>(
            gq, gk, nullptr, gsc, SS, SS, CC,
            (long)SS * CC, (long)SS * CC, (long)SS * SS);
        // top-k threshold + masked softmax (in place, applies temp)
        topk_softmax<<<dim3(SS, BB * HH), 256>>>(gsc, temp + l * HH);
        // attn @ V -> (B,H,S,C)
        gemm_attnv<<<dim3(1, SS / 64, BB * HH), 256>>>(gsc, gv, gao);
        // (B,H,S,C) -> (B,S,D)
        permute_ao<<<(BB * SS * DD) / 256, 256>>>(gao, gaop);
        // proj + residual into x
        gemm_xwt<false, false, true><<<dim3(DD / 64, NBS / 64, 1), 256>>>(
            gaop, proj_w + (size_t)l * DD * DD, nullptr, gx,
            NBS, DD, DD, 0, 0, 0);
        // ln2
        ln_kernel<<<NBS, 128>>>(gx, ln2_w + l * DD, ln2_b + l * DD, gln);
        // mlp fc1 + gelu
        gemm_xwt<false, true, false><<<dim3(MLPD / 64, NBS / 64, 1), 256>>>(
            gln, mlp_w1 + (size_t)l * MLPD * DD, mlp_b1 + l * MLPD, gmlp,
            NBS, MLPD, DD, 0, 0, 0);
        // mlp fc2 + bias + residual into x
        gemm_xwt<false, false, true><<<dim3(DD / 64, NBS / 64, 1), 256>>>(
            gmlp, mlp_w2 + (size_t)l * DD * MLPD, mlp_b2 + l * DD, gx,
            NBS, DD, MLPD, 0, 0, 0);
    }
    // final layernorm -> output
    ln_kernel<<<NBS, 128>>>(gx, lnf_w, lnf_b, out);
}

// round 3
// speedup vs baseline: 1.3272x; 1.3272x over previous
#include <cuda_runtime.h>
#include <math.h>

#define BB   4
#define SS   1024
#define DD   512
#define HH   8
#define CC   64
#define MLPD 2048
#define LL   4
#define TOPKK 256
#define D3   (3*DD)

// ---------------- scratch (static device globals; no dynamic allocation) ----
__device__ float g_x  [BB*SS*DD];                  // residual stream
__device__ float g_ln [BB*SS*DD];                  // layernorm output
__device__ float g_qkv[(size_t)BB*D3*SS];          // (B, 3D, S)
__device__ float g_q  [BB*HH*SS*CC];               // (B,H,S,C) normalized
__device__ float g_k  [BB*HH*SS*CC];
__device__ float g_v  [BB*HH*SS*CC];
__device__ float g_sc [(size_t)BB*HH*SS*SS];       // scores / probs (B,H,S,S)
__device__ float g_ao [BB*HH*SS*CC];               // attn out (B,H,S,C)
__device__ float g_aop[BB*SS*DD];                  // attn out (B,S,D)
__device__ float g_mlp[(size_t)BB*SS*MLPD];        // mlp hidden

// ---------------- helpers ----------------
__device__ __forceinline__ float geluf(float x) {
    return 0.5f * x * (1.0f + erff(x * 0.70710678118654752440f));
}
__device__ __forceinline__ unsigned f2key(float f) {
    unsigned u = __float_as_uint(f);
    return (u & 0x80000000u) ? ~u : (u | 0x80000000u);
}
__device__ __forceinline__ float key2f(unsigned k) {
    unsigned u = (k & 0x80000000u) ? (k & 0x7FFFFFFFu) : ~k;
    return __uint_as_float(u);
}
__device__ __forceinline__ float tf32r(float x) {
    unsigned u;
    asm("cvt.rna.tf32.f32 %0, %1;" : "=r"(u) : "f"(x));
    return __uint_as_float(u);
}
__device__ __forceinline__ void mma_tf32(float c[4], const unsigned a[4],
                                         const unsigned b[2]) {
    asm volatile(
        "mma.sync.aligned.m16n8k8.row.col.f32.tf32.tf32.f32 "
        "{%0,%1,%2,%3}, {%4,%5,%6,%7}, {%8,%9}, {%0,%1,%2,%3};"
        : "+f"(c[0]), "+f"(c[1]), "+f"(c[2]), "+f"(c[3])
        : "r"(a[0]), "r"(a[1]), "r"(a[2]), "r"(a[3]), "r"(b[0]), "r"(b[1]));
}

// ---------------- x = x_in + pos (broadcast over batch) ----------------
__global__ void add_pos_kernel(const float* __restrict__ x,
                               const float* __restrict__ pos,
                               float* __restrict__ out, int total, int per_b) {
    int i = blockIdx.x * blockDim.x + threadIdx.x;
    if (i < total) out[i] = x[i] + pos[i % per_b];
}

// ---------------- layernorm over D=512, one block (128 thr) per row ---------
__global__ void ln_kernel(const float* __restrict__ in,
                          const float* __restrict__ w,
                          const float* __restrict__ b,
                          float* __restrict__ out) {
    int row = blockIdx.x;
    const float* xr = in + (size_t)row * DD;
    float* yr = out + (size_t)row * DD;
    int tid = threadIdx.x;            // 128 threads
    float v[4], s = 0.f, sq = 0.f;
#pragma unroll
    for (int i = 0; i < 4; i++) {
        v[i] = xr[tid + i * 128];
        s += v[i]; sq += v[i] * v[i];
    }
    __shared__ float rs[32], rq[32];
#pragma unroll
    for (int o = 16; o; o >>= 1) {
        s  += __shfl_down_sync(0xFFFFFFFFu, s,  o);
        sq += __shfl_down_sync(0xFFFFFFFFu, sq, o);
    }
    int warp = tid >> 5, lane = tid & 31;
    if (lane == 0) { rs[warp] = s; rq[warp] = sq; }
    __syncthreads();
    if (tid == 0) {
        float a = 0.f, c = 0.f;
        for (int i = 0; i < 4; i++) { a += rs[i]; c += rq[i]; }
        rs[0] = a; rq[0] = c;
    }
    __syncthreads();
    float mu   = rs[0] * (1.0f / DD);
    float var  = rq[0] * (1.0f / DD) - mu * mu;
    float rstd = rsqrtf(var + 1e-6f);
#pragma unroll
    for (int i = 0; i < 4; i++) {
        int d = tid + i * 128;
        yr[d] = (v[i] - mu) * rstd * w[d] + b[d];
    }
}

// ====================== tensor-core TF32 (3x split) GEMM =====================
// C(r,q) = sum_k X(r,k) * W(q,k)   with X:(N,K) row-major.
// B_MMAJOR=false: W:(M,K) row-major (weights).  B_MMAJOR=true: W:(K,M) (= V).
// Block tile: 128(r) x QT(q), BK=16.  8 warps of (RWxQW) = (64x32) / (32x32).
// 3xTF32: each operand split hi/lo at staging; acc += aH*bH + aH*bL + aL*bH.
template <int QT, bool TRANS_OUT, bool GELU_ACT, bool RESID, bool B_MMAJOR>
__global__ void __launch_bounds__(256)
gemm_tc(const float* __restrict__ Xb, const float* __restrict__ Wb,
        const float* __restrict__ bias, float* __restrict__ Yb,
        int N, int M, int K, long xs, long ws, long ys) {
    constexpr int BK = 16;
    constexpr int PAD = 4;
    constexpr int LDS_ = BK + PAD;   // 20
    constexpr int RW = (QT == 128) ? 64 : 32;
    constexpr int RTILES = RW / 16;  // 4 or 2

    const float* X = Xb + (size_t)blockIdx.z * xs;
    const float* W = Wb + (size_t)blockIdx.z * ws;
    float* Y = Yb + (size_t)blockIdx.z * ys;

    __shared__ float XsH[128][LDS_], XsL[128][LDS_];
    __shared__ float WsH[QT][LDS_],  WsL[QT][LDS_];

    const int tid  = threadIdx.x;
    const int lane = tid & 31;
    const int warp = tid >> 5;
    const int wr = (QT == 128) ? (warp >> 2) : (warp >> 1);
    const int wq = (QT == 128) ? (warp & 3)  : (warp & 1);
    const int r_base = wr * RW;
    const int q_base = wq * 32;
    const int gr = lane >> 2;    // group row 0..7
    const int gc = lane & 3;     // 0..3

    const int q0 = blockIdx.x * QT;
    const int n0 = blockIdx.y * 128;

    float acc[RTILES][4][4];
#pragma unroll
    for (int i = 0; i < RTILES; i++)
#pragma unroll
        for (int j = 0; j < 4; j++)
#pragma unroll
            for (int t = 0; t < 4; t++) acc[i][j][t] = 0.f;

    for (int k0 = 0; k0 < K; k0 += BK) {
        // ---- stage X tile (128 x 16) as hi/lo ----
#pragma unroll
        for (int i = 0; i < 2; i++) {
            int f = tid + i * 256;            // 512 float4
            int row = f >> 2;
            int kc = (f & 3) * 4;
            float4 v = *(const float4*)(X + (size_t)(n0 + row) * K + k0 + kc);
            float h0 = tf32r(v.x), h1 = tf32r(v.y), h2 = tf32r(v.z), h3 = tf32r(v.w);
            XsH[row][kc+0] = h0; XsH[row][kc+1] = h1;
            XsH[row][kc+2] = h2; XsH[row][kc+3] = h3;
            XsL[row][kc+0] = tf32r(v.x - h0); XsL[row][kc+1] = tf32r(v.y - h1);
            XsL[row][kc+2] = tf32r(v.z - h2); XsL[row][kc+3] = tf32r(v.w - h3);
        }
        // ---- stage W tile (QT x 16) as hi/lo ----
        if (!B_MMAJOR) {
#pragma unroll
            for (int i = 0; i < QT * BK / 4 / 256; i++) {
                int f = tid + i * 256;
                int row = f >> 2;
                int kc = (f & 3) * 4;
                float4 v = *(const float4*)(W + (size_t)(q0 + row) * K + k0 + kc);
                float h0 = tf32r(v.x), h1 = tf32r(v.y), h2 = tf32r(v.z), h3 = tf32r(v.w);
                WsH[row][kc+0] = h0; WsH[row][kc+1] = h1;
                WsH[row][kc+2] = h2; WsH[row][kc+3] = h3;
                WsL[row][kc+0] = tf32r(v.x - h0); WsL[row][kc+1] = tf32r(v.y - h1);
                WsL[row][kc+2] = tf32r(v.z - h2); WsL[row][kc+3] = tf32r(v.w - h3);
            }
        } else {
            // W global is (K, M): read along m, transpose into Ws[q][k]
            constexpr int F4 = BK * QT / 4;   // 256 (QT=64) or 512
#pragma unroll
            for (int i = 0; i < F4 / 256; i++) {
                int f = tid + i * 256;
                int krow = f / (QT / 4);
                int mc = (f % (QT / 4)) * 4;
                float4 v = *(const float4*)(W + (size_t)(k0 + krow) * M + q0 + mc);
                float h0 = tf32r(v.x), h1 = tf32r(v.y), h2 = tf32r(v.z), h3 = tf32r(v.w);
                WsH[mc+0][krow] = h0; WsL[mc+0][krow] = tf32r(v.x - h0);
                WsH[mc+1][krow] = h1; WsL[mc+1][krow] = tf32r(v.y - h1);
                WsH[mc+2][krow] = h2; WsL[mc+2][krow] = tf32r(v.z - h2);
                WsH[mc+3][krow] = h3; WsL[mc+3][krow] = tf32r(v.w - h3);
            }
        }
        __syncthreads();

#pragma unroll
        for (int ks = 0; ks < BK; ks += 8) {
            unsigned aH[RTILES][4], aL[RTILES][4];
            unsigned bH[4][2], bL[4][2];
#pragma unroll
            for (int i = 0; i < RTILES; i++) {
                int rr = r_base + i * 16 + gr;
                aH[i][0] = __float_as_uint(XsH[rr][ks + gc]);
                aH[i][1] = __float_as_uint(XsH[rr + 8][ks + gc]);
                aH[i][2] = __float_as_uint(XsH[rr][ks + gc + 4]);
                aH[i][3] = __float_as_uint(XsH[rr + 8][ks + gc + 4]);
                aL[i][0] = __float_as_uint(XsL[rr][ks + gc]);
                aL[i][1] = __float_as_uint(XsL[rr + 8][ks + gc]);
                aL[i][2] = __float_as_uint(XsL[rr][ks + gc + 4]);
                aL[i][3] = __float_as_uint(XsL[rr + 8][ks + gc + 4]);
            }
#pragma unroll
            for (int j = 0; j < 4; j++) {
                int qq = q_base + j * 8 + gr;
                bH[j][0] = __float_as_uint(WsH[qq][ks + gc]);
                bH[j][1] = __float_as_uint(WsH[qq][ks + gc + 4]);
                bL[j][0] = __float_as_uint(WsL[qq][ks + gc]);
                bL[j][1] = __float_as_uint(WsL[qq][ks + gc + 4]);
            }
#pragma unroll
            for (int i = 0; i < RTILES; i++)
#pragma unroll
                for (int j = 0; j < 4; j++) {
                    mma_tf32(acc[i][j], aH[i], bH[j]);
                    mma_tf32(acc[i][j], aH[i], bL[j]);
                    mma_tf32(acc[i][j], aL[i], bH[j]);
                }
        }
        __syncthreads();
    }

    // ---- epilogue ----
#pragma unroll
    for (int i = 0; i < RTILES; i++) {
#pragma unroll
        for (int j = 0; j < 4; j++) {
#pragma unroll
            for (int t = 0; t < 4; t++) {
                int r = n0 + r_base + i * 16 + gr + ((t >= 2) ? 8 : 0);
                int q = q0 + q_base + j * 8 + 2 * gc + (t & 1);
                float v = acc[i][j][t];
                if (bias) v += bias[q];
                if (GELU_ACT) v = geluf(v);
                size_t idx = TRANS_OUT ? ((size_t)q * N + r) : ((size_t)r * M + q);
                if (RESID) Y[idx] += v; else Y[idx] = v;
            }
        }
    }
}

// ------- depthwise conv3 + head split + (q,k) L2-normalize ----------------
// grid: (S/64, 3*H, B). block 256. q/k/v outputs in (B,H,S,C).
__global__ void conv_heads(const float* __restrict__ qkv,
                           const float* __restrict__ dw,  // (3D, 3)
                           float* __restrict__ q,
                           float* __restrict__ k,
                           float* __restrict__ v) {
    int b = blockIdx.z;
    int part = blockIdx.y / HH, h = blockIdx.y % HH;
    int s0 = blockIdx.x * 64;
    int ch0 = part * DD + h * CC;
    __shared__ float tin[64][66];
    __shared__ float ct[64][65];
    int tid = threadIdx.x;

    for (int idx = tid; idx < 64 * 66; idx += 256) {
        int c = idx / 66, j = idx % 66;
        int s = s0 + j - 1;
        float val = 0.f;
        if (s >= 0 && s < SS) val = qkv[((size_t)b * D3 + ch0 + c) * SS + s];
        tin[c][j] = val;
    }
    __syncthreads();
    for (int idx = tid; idx < 4096; idx += 256) {
        int c = idx >> 6, s = idx & 63;
        const float* wp = dw + (ch0 + c) * 3;
        ct[c][s] = wp[0] * tin[c][s] + wp[1] * tin[c][s + 1] + wp[2] * tin[c][s + 2];
    }
    __syncthreads();
    float* out = (part == 0 ? q : (part == 1 ? k : v));
    out += ((size_t)(b * HH + h) * SS + s0) * CC;
    if (part == 2) {
        for (int idx = tid; idx < 4096; idx += 256) {
            int s = idx >> 6, c = idx & 63;
            out[s * CC + c] = ct[c][s];
        }
    } else {
        __shared__ float red[4][64];
        __shared__ float rnorm[64];
        int tx = tid & 63, ty = tid >> 6;
        float p = 0.f;
        for (int c = ty * 16; c < ty * 16 + 16; c++) {
            float u = ct[c][tx];
            p += u * u;
        }
        red[ty][tx] = p;
        __syncthreads();
        if (ty == 0) {
            float nn = red[0][tx] + red[1][tx] + red[2][tx] + red[3][tx];
            rnorm[tx] = 1.f / fmaxf(sqrtf(nn), 1e-12f);
        }
        __syncthreads();
        for (int idx = tid; idx < 4096; idx += 256) {
            int s = idx >> 6, c = idx & 63;
            out[s * CC + c] = ct[c][s] * rnorm[s];
        }
    }
}

// ------- top-k (exact radix select on float keys) + masked softmax ---------
// grid: (S, B*H), block 256. In-place on scores row (scaled by temp[h]).
__global__ void topk_softmax(float* __restrict__ scores,
                             const float* __restrict__ temp) {
    int bh = blockIdx.y;
    int h = bh % HH;
    int s = blockIdx.x;
    float* row = scores + ((size_t)bh * SS + s) * SS;
    float t = temp[h];
    __shared__ unsigned keys[SS];
    __shared__ unsigned hist[256];
    __shared__ float fred[256];
    __shared__ unsigned sh_prefix;
    __shared__ int sh_k;
    int tid = threadIdx.x;

    float lmax = -3.4e38f;
#pragma unroll
    for (int i = 0; i < 4; i++) {
        int idx = tid + i * 256;
        float f = row[idx] * t;
        keys[idx] = f2key(f);
        lmax = fmaxf(lmax, f);
    }
    fred[tid] = lmax;
    __syncthreads();
    for (int o = 128; o; o >>= 1) {
        if (tid < o) fred[tid] = fmaxf(fred[tid], fred[tid + o]);
        __syncthreads();
    }
    float maxv = fred[0];
    if (tid == 0) { sh_prefix = 0u; sh_k = TOPKK; }
    __syncthreads();

    for (int pass = 0; pass < 4; pass++) {
        int shift = 24 - 8 * pass;
        hist[tid] = 0u;
        __syncthreads();
        unsigned pref = sh_prefix;
        unsigned mask = (pass == 0) ? 0u : (0xFFFFFFFFu << (shift + 8));
#pragma unroll
        for (int i = 0; i < 4; i++) {
            unsigned key = keys[tid + i * 256];
            if ((key & mask) == pref) atomicAdd(&hist[(key >> shift) & 255], 1u);
        }
        __syncthreads();
        if (tid == 0) {
            int kk = sh_k;
            int d = 255;
            for (; d > 0; d--) {
                int c = (int)hist[d];
                if (kk <= c) break;
                kk -= c;
            }
            sh_k = kk;
            sh_prefix = pref | ((unsigned)d << shift);
        }
        __syncthreads();
    }
    float vstar = key2f(sh_prefix);
    float m = fminf(fmaxf(maxv, -10000.f), 10000.f);

    float lsum = 0.f;
#pragma unroll
    for (int i = 0; i < 4; i++) {
        int idx = tid + i * 256;
        float f = key2f(keys[idx]);
        float p = (f >= vstar) ? fminf(fmaxf(f, -10000.f), 10000.f) : -10000.f;
        float e = expf(p - m);
        ((float*)keys)[idx] = e;   // each thread rewrites its own slots only
        lsum += e;
    }
    fred[tid] = lsum;
    __syncthreads();
    for (int o = 128; o; o >>= 1) {
        if (tid < o) fred[tid] += fred[tid + o];
        __syncthreads();
    }
    float inv = 1.f / fred[0];
#pragma unroll
    for (int i = 0; i < 4; i++) {
        int idx = tid + i * 256;
        row[idx] = ((float*)keys)[idx] * inv;
    }
}

// ------- (B,H,S,C) -> (B,S,D) ----------------------------------------------
__global__ void permute_ao(const float* __restrict__ ao, float* __restrict__ out) {
    int idx = blockIdx.x * 256 + threadIdx.x;
    int d = idx % DD;
    int bs = idx / DD;
    int si = bs % SS, b = bs / SS;
    int h = d / CC, c = d % CC;
    out[idx] = ao[(((size_t)(b * HH + h)) * SS + si) * CC + c];
}

// ---------------- host orchestration ----------------------------------------
extern "C" void kernel_launch(void* const* d_in, const int* in_sizes, int n_in,
                              void* d_out, int out_size) {
    (void)in_sizes; (void)n_in; (void)out_size;
    const float* x      = (const float*)d_in[0];
    const float* pos    = (const float*)d_in[1];
    const float* ln1_w  = (const float*)d_in[2];
    const float* ln1_b  = (const float*)d_in[3];
    const float* qkv_w  = (const float*)d_in[4];
    const float* dw_w   = (const float*)d_in[5];
    const float* temp   = (const float*)d_in[6];
    const float* proj_w = (const float*)d_in[7];
    const float* ln2_w  = (const float*)d_in[8];
    const float* ln2_b  = (const float*)d_in[9];
    const float* mlp_w1 = (const float*)d_in[10];
    const float* mlp_b1 = (const float*)d_in[11];
    const float* mlp_w2 = (const float*)d_in[12];
    const float* mlp_b2 = (const float*)d_in[13];
    const float* lnf_w  = (const float*)d_in[14];
    const float* lnf_b  = (const float*)d_in[15];
    float* out = (float*)d_out;

    float *gx, *gln, *gqkv, *gq, *gk, *gv, *gsc, *gao, *gaop, *gmlp;
    cudaGetSymbolAddress((void**)&gx,   g_x);
    cudaGetSymbolAddress((void**)&gln,  g_ln);
    cudaGetSymbolAddress((void**)&gqkv, g_qkv);
    cudaGetSymbolAddress((void**)&gq,   g_q);
    cudaGetSymbolAddress((void**)&gk,   g_k);
    cudaGetSymbolAddress((void**)&gv,   g_v);
    cudaGetSymbolAddress((void**)&gsc,  g_sc);
    cudaGetSymbolAddress((void**)&gao,  g_ao);
    cudaGetSymbolAddress((void**)&gaop, g_aop);
    cudaGetSymbolAddress((void**)&gmlp, g_mlp);

    const int NBS = BB * SS;           // 4096 rows
    add_pos_kernel<<<(BB * SS * DD + 255) / 256, 256>>>(x, pos, gx, BB * SS * DD, SS * DD);

    for (int l = 0; l < LL; l++) {
        // ln1
        ln_kernel<<<NBS, 128>>>(gx, ln1_w + l * DD, ln1_b + l * DD, gln);
        // qkv 1x1 conv: per batch (1536 x 512) @ (512 x 1024) -> (B, 3D, S)
        gemm_tc<128, true, false, false, false><<<dim3(D3 / 128, SS / 128, BB), 256>>>(
            gln, qkv_w + (size_t)l * D3 * DD, nullptr, gqkv,
            SS, D3, DD, (long)SS * DD, 0, (long)D3 * SS);
        // depthwise conv3 + head split + q/k normalize
        conv_heads<<<dim3(SS / 64, 3 * HH, BB), 256>>>(
            gqkv, dw_w + (size_t)l * D3 * 3, gq, gk, gv);
        // scores = q k^T  (batched over B*H, K = 64)
        gemm_tc<128, false, false, false, false><<<dim3(SS / 128, SS / 128, BB * HH), 256>>>(
            gq, gk, nullptr, gsc, SS, SS, CC,
            (long)SS * CC, (long)SS * CC, (long)SS * SS);
        // top-k threshold + masked softmax (in place, applies temp)
        topk_softmax<<<dim3(SS, BB * HH), 256>>>(gsc, temp + l * HH);
        // attn @ V -> (B,H,S,C): P(S,S) @ V(S,C), V is (K,M) "m-major"
        gemm_tc<64, false, false, false, true><<<dim3(1, SS / 128, BB * HH), 256>>>(
            gsc, gv, nullptr, gao, SS, CC, SS,
            (long)SS * SS, (long)SS * CC, (long)SS * CC);
        // (B,H,S,C) -> (B,S,D)
        permute_ao<<<(BB * SS * DD) / 256, 256>>>(gao, gaop);
        // proj + residual into x
        gemm_tc<128, false, false, true, false><<<dim3(DD / 128, NBS / 128, 1), 256>>>(
            gaop, proj_w + (size_t)l * DD * DD, nullptr, gx,
            NBS, DD, DD, 0, 0, 0);
        // ln2
        ln_kernel<<<NBS, 128>>>(gx, ln2_w + l * DD, ln2_b + l * DD, gln);
        // mlp fc1 + gelu
        gemm_tc<128, false, true, false, false><<<dim3(MLPD / 128, NBS / 128, 1), 256>>>(
            gln, mlp_w1 + (size_t)l * MLPD * DD, mlp_b1 + l * MLPD, gmlp,
            NBS, MLPD, DD, 0, 0, 0);
        // mlp fc2 + bias + residual into x
        gemm_tc<128, false, false, true, false><<<dim3(DD / 128, NBS / 128, 1), 256>>>(
            gmlp, mlp_w2 + (size_t)l * DD * MLPD, mlp_b2 + l * DD, gx,
            NBS, DD, MLPD, 0, 0, 0);
    }
    // final layernorm -> output
    ln_kernel<<<NBS, 128>>>(gx, lnf_w, lnf_b, out);
}

// round 7
// speedup vs baseline: 1.8683x; 1.4077x over previous
#include <cuda_runtime.h>
#include <cuda_bf16.h>
#include <math.h>

#define BB   4
#define SS   1024
#define DD   512
#define HH   8
#define CC   64
#define MLPD 2048
#define LL   4
#define TOPKK 256
#define D3   (3*DD)

// ---------------- scratch (static device globals; no dynamic allocation) ----
__device__ float g_x  [BB*SS*DD];                  // residual stream
__device__ float g_ln [BB*SS*DD];                  // layernorm output
__device__ float g_qkv[(size_t)BB*D3*SS];          // (B, 3D, S)
__device__ float g_q  [BB*HH*SS*CC];               // (B,H,S,C) normalized
__device__ float g_k  [BB*HH*SS*CC];
__device__ float g_v  [BB*HH*SS*CC];
__device__ float g_sc [(size_t)BB*HH*SS*SS];       // scores / probs (B,H,S,S)
__device__ float g_ao [BB*HH*SS*CC];               // attn out (B,H,S,C)
__device__ float g_mlp[(size_t)BB*SS*MLPD];        // mlp hidden

// ---------------- helpers ----------------
__device__ __forceinline__ float geluf(float x) {
    return 0.5f * x * (1.0f + erff(x * 0.70710678118654752440f));
}
__device__ __forceinline__ unsigned f2key(float f) {
    unsigned u = __float_as_uint(f);
    return (u & 0x80000000u) ? ~u : (u | 0x80000000u);
}
__device__ __forceinline__ float key2f(unsigned k) {
    unsigned u = (k & 0x80000000u) ? (k & 0x7FFFFFFFu) : ~k;
    return __uint_as_float(u);
}
// bf16 mma: D += A(16x16,row) * B(16x8,col)
__device__ __forceinline__ void mma_bf16(float c[4], const unsigned a[4],
                                         const unsigned b[2]) {
    asm volatile(
        "mma.sync.aligned.m16n8k16.row.col.f32.bf16.bf16.f32 "
        "{%0,%1,%2,%3}, {%4,%5,%6,%7}, {%8,%9}, {%0,%1,%2,%3};"
        : "+f"(c[0]), "+f"(c[1]), "+f"(c[2]), "+f"(c[3])
        : "r"(a[0]), "r"(a[1]), "r"(a[2]), "r"(a[3]), "r"(b[0]), "r"(b[1]));
}
// split two floats into packed bf16 hi / lo pairs (hi = rn(x), lo = rn(x-hi))
__device__ __forceinline__ void split2(float x, float y,
                                       unsigned& hi, unsigned& lo) {
    __nv_bfloat162 h = __floats2bfloat162_rn(x, y);
    float hx = __bfloat162float(h.x), hy = __bfloat162float(h.y);
    __nv_bfloat162 l = __floats2bfloat162_rn(x - hx, y - hy);
    hi = *(unsigned*)&h;
    lo = *(unsigned*)&l;
}

// ---------------- x = x_in + pos (broadcast over batch) ----------------
__global__ void add_pos_kernel(const float* __restrict__ x,
                               const float* __restrict__ pos,
                               float* __restrict__ out, int total, int per_b) {
    int i = blockIdx.x * blockDim.x + threadIdx.x;
    if (i < total) out[i] = x[i] + pos[i % per_b];
}

// ---------------- layernorm over D=512, one block (128 thr) per row ---------
__global__ void ln_kernel(const float* __restrict__ in,
                          const float* __restrict__ w,
                          const float* __restrict__ b,
                          float* __restrict__ out) {
    int row = blockIdx.x;
    const float* xr = in + (size_t)row * DD;
    float* yr = out + (size_t)row * DD;
    int tid = threadIdx.x;            // 128 threads
    float v[4], s = 0.f, sq = 0.f;
#pragma unroll
    for (int i = 0; i < 4; i++) {
        v[i] = xr[tid + i * 128];
        s += v[i]; sq += v[i] * v[i];
    }
    __shared__ float rs[32], rq[32];
#pragma unroll
    for (int o = 16; o; o >>= 1) {
        s  += __shfl_down_sync(0xFFFFFFFFu, s,  o);
        sq += __shfl_down_sync(0xFFFFFFFFu, sq, o);
    }
    int warp = tid >> 5, lane = tid & 31;
    if (lane == 0) { rs[warp] = s; rq[warp] = sq; }
    __syncthreads();
    if (tid == 0) {
        float a = 0.f, c = 0.f;
        for (int i = 0; i < 4; i++) { a += rs[i]; c += rq[i]; }
        rs[0] = a; rq[0] = c;
    }
    __syncthreads();
    float mu   = rs[0] * (1.0f / DD);
    float var  = rq[0] * (1.0f / DD) - mu * mu;
    float rstd = rsqrtf(var + 1e-6f);
#pragma unroll
    for (int i = 0; i < 4; i++) {
        int d = tid + i * 128;
        yr[d] = (v[i] - mu) * rstd * w[d] + b[d];
    }
}

// =================== tensor-core bf16x2-split GEMM ==========================
// C(r,q) = sum_k X(r,k) * W(q,k)   with X:(N,K) row-major.
// B_MMAJOR=false: W:(M,K) row-major.  B_MMAJOR=true: W:(K,M) (= V).
// X_AOPERM: X is attn-out in (B,H,S,C); row r=(b,s), k=(h,c).
// Block tile: 128(r) x QT(q), BK=32.  8 warps of (RW x 32).
// Split: x = hi + lo (bf16 each); acc += aH*bH + aH*bL + aL*bH (fp32 acc).
template <int QT, bool TRANS_OUT, bool GELU_ACT, bool RESID, bool B_MMAJOR,
          bool X_AOPERM>
__global__ void __launch_bounds__(256)
gemm_tc(const float* __restrict__ Xb, const float* __restrict__ Wb,
        const float* __restrict__ bias, float* __restrict__ Yb,
        int N, int M, int K, long xs, long ws, long ys) {
    constexpr int BK  = 32;
    constexpr int LDB = BK + 8;      // 40 bf16 -> 20-word row stride, conflict-free
    constexpr int RW = (QT == 128) ? 64 : 32;
    constexpr int RTILES = RW / 16;  // 4 or 2

    const float* X = Xb + (size_t)blockIdx.z * xs;
    const float* W = Wb + (size_t)blockIdx.z * ws;
    float* Y = Yb + (size_t)blockIdx.z * ys;

    __shared__ __nv_bfloat16 XsH[128][LDB], XsL[128][LDB];
    __shared__ __nv_bfloat16 WsH[QT][LDB],  WsL[QT][LDB];

    const int tid  = threadIdx.x;
    const int lane = tid & 31;
    const int warp = tid >> 5;
    const int wr = (QT == 128) ? (warp >> 2) : (warp >> 1);
    const int wq = (QT == 128) ? (warp & 3)  : (warp & 1);
    const int r_base = wr * RW;
    const int q_base = wq * 32;
    const int gr = lane >> 2;    // 0..7
    const int gc = lane & 3;     // 0..3

    const int q0 = blockIdx.x * QT;
    const int n0 = blockIdx.y * 128;

    float acc[RTILES][4][4];
#pragma unroll
    for (int i = 0; i < RTILES; i++)
#pragma unroll
        for (int j = 0; j < 4; j++)
#pragma unroll
            for (int t = 0; t < 4; t++) acc[i][j][t] = 0.f;

    for (int k0 = 0; k0 < K; k0 += BK) {
        // ---- stage X tile (128 x 32) as bf16 hi/lo ----
#pragma unroll
        for (int i = 0; i < 4; i++) {
            int f = tid + i * 256;           // 1024 float4
            int row = f >> 3;
            int kc = (f & 7) * 4;
            const float* src;
            if (X_AOPERM) {
                int r = n0 + row;
                int b = r >> 10, s = r & 1023;
                int k = k0 + kc;
                int h = k >> 6, c = k & 63;
                src = X + ((((size_t)b * HH + h) * SS + s) * CC + c);
            } else {
                src = X + (size_t)(n0 + row) * K + k0 + kc;
            }
            float4 v = *(const float4*)src;
            unsigned h01, l01, h23, l23;
            split2(v.x, v.y, h01, l01);
            split2(v.z, v.w, h23, l23);
            *(unsigned*)&XsH[row][kc]     = h01;
            *(unsigned*)&XsH[row][kc + 2] = h23;
            *(unsigned*)&XsL[row][kc]     = l01;
            *(unsigned*)&XsL[row][kc + 2] = l23;
        }
        // ---- stage W tile (QT x 32) as bf16 hi/lo ----
        if (!B_MMAJOR) {
#pragma unroll
            for (int i = 0; i < QT / 32; i++) {
                int f = tid + i * 256;
                int row = f >> 3;
                int kc = (f & 7) * 4;
                float4 v = *(const float4*)(W + (size_t)(q0 + row) * K + k0 + kc);
                unsigned h01, l01, h23, l23;
                split2(v.x, v.y, h01, l01);
                split2(v.z, v.w, h23, l23);
                *(unsigned*)&WsH[row][kc]     = h01;
                *(unsigned*)&WsH[row][kc + 2] = h23;
                *(unsigned*)&WsL[row][kc]     = l01;
                *(unsigned*)&WsL[row][kc + 2] = l23;
            }
        } else {
            // W global is (K, M): read along m, transpose into Ws[q][k]
#pragma unroll
            for (int i = 0; i < (BK * QT / 4) / 256; i++) {
                int f = tid + i * 256;
                int krow = f / (QT / 4);
                int mc = (f % (QT / 4)) * 4;
                float4 v = *(const float4*)(W + (size_t)(k0 + krow) * M + q0 + mc);
                __nv_bfloat16 h;
                h = __float2bfloat16_rn(v.x);
                WsH[mc + 0][krow] = h;
                WsL[mc + 0][krow] = __float2bfloat16_rn(v.x - __bfloat162float(h));
                h = __float2bfloat16_rn(v.y);
                WsH[mc + 1][krow] = h;
                WsL[mc + 1][krow] = __float2bfloat16_rn(v.y - __bfloat162float(h));
                h = __float2bfloat16_rn(v.z);
                WsH[mc + 2][krow] = h;
                WsL[mc + 2][krow] = __float2bfloat16_rn(v.z - __bfloat162float(h));
                h = __float2bfloat16_rn(v.w);
                WsH[mc + 3][krow] = h;
                WsL[mc + 3][krow] = __float2bfloat16_rn(v.w - __bfloat162float(h));
            }
        }
        __syncthreads();

#pragma unroll
        for (int ks = 0; ks < BK; ks += 16) {
            unsigned aH[RTILES][4], aL[RTILES][4];
            unsigned bH[4][2], bL[4][2];
#pragma unroll
            for (int i = 0; i < RTILES; i++) {
                int rr = r_base + i * 16 + gr;
                int kk = ks + 2 * gc;
                aH[i][0] = *(const unsigned*)&XsH[rr][kk];
                aH[i][1] = *(const unsigned*)&XsH[rr + 8][kk];
                aH[i][2] = *(const unsigned*)&XsH[rr][kk + 8];
                aH[i][3] = *(const unsigned*)&XsH[rr + 8][kk + 8];
                aL[i][0] = *(const unsigned*)&XsL[rr][kk];
                aL[i][1] = *(const unsigned*)&XsL[rr + 8][kk];
                aL[i][2] = *(const unsigned*)&XsL[rr][kk + 8];
                aL[i][3] = *(const unsigned*)&XsL[rr + 8][kk + 8];
            }
#pragma unroll
            for (int j = 0; j < 4; j++) {
                int qq = q_base + j * 8 + gr;
                int kk = ks + 2 * gc;
                bH[j][0] = *(const unsigned*)&WsH[qq][kk];
                bH[j][1] = *(const unsigned*)&WsH[qq][kk + 8];
                bL[j][0] = *(const unsigned*)&WsL[qq][kk];
                bL[j][1] = *(const unsigned*)&WsL[qq][kk + 8];
            }
#pragma unroll
            for (int i = 0; i < RTILES; i++)
#pragma unroll
                for (int j = 0; j < 4; j++) {
                    mma_bf16(acc[i][j], aH[i], bH[j]);
                    mma_bf16(acc[i][j], aH[i], bL[j]);
                    mma_bf16(acc[i][j], aL[i], bH[j]);
                }
        }
        __syncthreads();
    }

    // ---- epilogue ----
#pragma unroll
    for (int i = 0; i < RTILES; i++) {
#pragma unroll
        for (int j = 0; j < 4; j++) {
#pragma unroll
            for (int t = 0; t < 4; t++) {
                int r = n0 + r_base + i * 16 + gr + ((t >= 2) ? 8 : 0);
                int q = q0 + q_base + j * 8 + 2 * gc + (t & 1);
                float v = acc[i][j][t];
                if (bias) v += bias[q];
                if (GELU_ACT) v = geluf(v);
                size_t idx = TRANS_OUT ? ((size_t)q * N + r) : ((size_t)r * M + q);
                if (RESID) Y[idx] += v; else Y[idx] = v;
            }
        }
    }
}

// ------- depthwise conv3 + head split + (q,k) L2-normalize ----------------
// grid: (S/64, 3*H, B). block 256. q/k/v outputs in (B,H,S,C).
__global__ void conv_heads(const float* __restrict__ qkv,
                           const float* __restrict__ dw,  // (3D, 3)
                           float* __restrict__ q,
                           float* __restrict__ k,
                           float* __restrict__ v) {
    int b = blockIdx.z;
    int part = blockIdx.y / HH, h = blockIdx.y % HH;
    int s0 = blockIdx.x * 64;
    int ch0 = part * DD + h * CC;
    __shared__ float tin[64][66];
    __shared__ float ct[64][65];
    int tid = threadIdx.x;

    for (int idx = tid; idx < 64 * 66; idx += 256) {
        int c = idx / 66, j = idx % 66;
        int s = s0 + j - 1;
        float val = 0.f;
        if (s >= 0 && s < SS) val = qkv[((size_t)b * D3 + ch0 + c) * SS + s];
        tin[c][j] = val;
    }
    __syncthreads();
    for (int idx = tid; idx < 4096; idx += 256) {
        int c = idx >> 6, s = idx & 63;
        const float* wp = dw + (ch0 + c) * 3;
        ct[c][s] = wp[0] * tin[c][s] + wp[1] * tin[c][s + 1] + wp[2] * tin[c][s + 2];
    }
    __syncthreads();
    float* out = (part == 0 ? q : (part == 1 ? k : v));
    out += ((size_t)(b * HH + h) * SS + s0) * CC;
    if (part == 2) {
        for (int idx = tid; idx < 4096; idx += 256) {
            int s = idx >> 6, c = idx & 63;
            out[s * CC + c] = ct[c][s];
        }
    } else {
        __shared__ float red[4][64];
        __shared__ float rnorm[64];
        int tx = tid & 63, ty = tid >> 6;
        float p = 0.f;
        for (int c = ty * 16; c < ty * 16 + 16; c++) {
            float u = ct[c][tx];
            p += u * u;
        }
        red[ty][tx] = p;
        __syncthreads();
        if (ty == 0) {
            float nn = red[0][tx] + red[1][tx] + red[2][tx] + red[3][tx];
            rnorm[tx] = 1.f / fmaxf(sqrtf(nn), 1e-12f);
        }
        __syncthreads();
        for (int idx = tid; idx < 4096; idx += 256) {
            int s = idx >> 6, c = idx & 63;
            out[s * CC + c] = ct[c][s] * rnorm[s];
        }
    }
}

// ------- top-k (exact radix select on float keys) + masked softmax ---------
// grid: (S, B*H), block 256. In-place on scores row (scaled by temp[h]).
__global__ void topk_softmax(float* __restrict__ scores,
                             const float* __restrict__ temp) {
    int bh = blockIdx.y;
    int h = bh % HH;
    int s = blockIdx.x;
    float* row = scores + ((size_t)bh * SS + s) * SS;
    float t = temp[h];
    __shared__ unsigned keys[SS];
    __shared__ unsigned hist[256];
    __shared__ unsigned sfx[256];
    __shared__ float fred[256];
    __shared__ unsigned sh_prefix;
    __shared__ int sh_k;
    int tid = threadIdx.x;

    float lmax = -3.4e38f;
#pragma unroll
    for (int i = 0; i < 4; i++) {
        int idx = tid + i * 256;
        float f = row[idx] * t;
        keys[idx] = f2key(f);
        lmax = fmaxf(lmax, f);
    }
    fred[tid] = lmax;
    __syncthreads();
    for (int o = 128; o; o >>= 1) {
        if (tid < o) fred[tid] = fmaxf(fred[tid], fred[tid + o]);
        __syncthreads();
    }
    float maxv = fred[0];
    if (tid == 0) { sh_prefix = 0u; sh_k = TOPKK; }
    __syncthreads();

    for (int pass = 0; pass < 4; pass++) {
        int shift = 24 - 8 * pass;
        hist[tid] = 0u;
        __syncthreads();
        unsigned pref = sh_prefix;
        int kk = sh_k;
        unsigned mask = (pass == 0) ? 0u : (0xFFFFFFFFu << (shift + 8));
#pragma unroll
        for (int i = 0; i < 4; i++) {
            unsigned key = keys[tid + i * 256];
            if ((key & mask) == pref) atomicAdd(&hist[(key >> shift) & 255], 1u);
        }
        __syncthreads();
        // parallel suffix-sum: sfx[d] = sum_{d'>=d} hist[d']
        sfx[tid] = hist[tid];
        __syncthreads();
        for (int o = 1; o < 256; o <<= 1) {
            unsigned v = sfx[tid];
            unsigned add = (tid + o < 256) ? sfx[tid + o] : 0u;
            __syncthreads();
            sfx[tid] = v + add;
            __syncthreads();
        }
        // unique digit d with sfx[d] >= kk > sfx[d+1]
        int above = (tid == 255) ? 0 : (int)sfx[tid + 1];
        if ((int)sfx[tid] >= kk && above < kk) {
            sh_prefix = pref | ((unsigned)tid << shift);
            sh_k = kk - above;
        }
        __syncthreads();
    }
    float vstar = key2f(sh_prefix);
    float m = fminf(fmaxf(maxv, -10000.f), 10000.f);

    float lsum = 0.f;
#pragma unroll
    for (int i = 0; i < 4; i++) {
        int idx = tid + i * 256;
        float f = key2f(keys[idx]);
        float p = (f >= vstar) ? fminf(fmaxf(f, -10000.f), 10000.f) : -10000.f;
        float e = expf(p - m);
        ((float*)keys)[idx] = e;   // each thread rewrites its own slots only
        lsum += e;
    }
    fred[tid] = lsum;
    __syncthreads();
    for (int o = 128; o; o >>= 1) {
        if (tid < o) fred[tid] += fred[tid + o];
        __syncthreads();
    }
    float inv = 1.f / fred[0];
#pragma unroll
    for (int i = 0; i < 4; i++) {
        int idx = tid + i * 256;
        row[idx] = ((float*)keys)[idx] * inv;
    }
}

// ---------------- host orchestration ----------------------------------------
extern "C" void kernel_launch(void* const* d_in, const int* in_sizes, int n_in,
                              void* d_out, int out_size) {
    (void)in_sizes; (void)n_in; (void)out_size;
    const float* x      = (const float*)d_in[0];
    const float* pos    = (const float*)d_in[1];
    const float* ln1_w  = (const float*)d_in[2];
    const float* ln1_b  = (const float*)d_in[3];
    const float* qkv_w  = (const float*)d_in[4];
    const float* dw_w   = (const float*)d_in[5];
    const float* temp   = (const float*)d_in[6];
    const float* proj_w = (const float*)d_in[7];
    const float* ln2_w  = (const float*)d_in[8];
    const float* ln2_b  = (const float*)d_in[9];
    const float* mlp_w1 = (const float*)d_in[10];
    const float* mlp_b1 = (const float*)d_in[11];
    const float* mlp_w2 = (const float*)d_in[12];
    const float* mlp_b2 = (const float*)d_in[13];
    const float* lnf_w  = (const float*)d_in[14];
    const float* lnf_b  = (const float*)d_in[15];
    float* out = (float*)d_out;

    float *gx, *gln, *gqkv, *gq, *gk, *gv, *gsc, *gao, *gmlp;
    cudaGetSymbolAddress((void**)&gx,   g_x);
    cudaGetSymbolAddress((void**)&gln,  g_ln);
    cudaGetSymbolAddress((void**)&gqkv, g_qkv);
    cudaGetSymbolAddress((void**)&gq,   g_q);
    cudaGetSymbolAddress((void**)&gk,   g_k);
    cudaGetSymbolAddress((void**)&gv,   g_v);
    cudaGetSymbolAddress((void**)&gsc,  g_sc);
    cudaGetSymbolAddress((void**)&gao,  g_ao);
    cudaGetSymbolAddress((void**)&gmlp, g_mlp);

    const int NBS = BB * SS;           // 4096 rows
    add_pos_kernel<<<(BB * SS * DD + 255) / 256, 256>>>(x, pos, gx, BB * SS * DD, SS * DD);

    for (int l = 0; l < LL; l++) {
        // ln1
        ln_kernel<<<NBS, 128>>>(gx, ln1_w + l * DD, ln1_b + l * DD, gln);
        // qkv 1x1 conv: per batch (1536 x 512) @ (512 x 1024) -> (B, 3D, S)
        gemm_tc<128, true, false, false, false, false>
            <<<dim3(D3 / 128, SS / 128, BB), 256>>>(
            gln, qkv_w + (size_t)l * D3 * DD, nullptr, gqkv,
            SS, D3, DD, (long)SS * DD, 0, (long)D3 * SS);
        // depthwise conv3 + head split + q/k normalize
        conv_heads<<<dim3(SS / 64, 3 * HH, BB), 256>>>(
            gqkv, dw_w + (size_t)l * D3 * 3, gq, gk, gv);
        // scores = q k^T  (batched over B*H, K = 64)
        gemm_tc<128, false, false, false, false, false>
            <<<dim3(SS / 128, SS / 128, BB * HH), 256>>>(
            gq, gk, nullptr, gsc, SS, SS, CC,
            (long)SS * CC, (long)SS * CC, (long)SS * SS);
        // top-k threshold + masked softmax (in place, applies temp)
        topk_softmax<<<dim3(SS, BB * HH), 256>>>(gsc, temp + l * HH);
        // attn @ V -> (B,H,S,C): P(S,S) @ V(S,C), V is (K,M) m-major
        gemm_tc<64, false, false, false, true, false>
            <<<dim3(1, SS / 128, BB * HH), 256>>>(
            gsc, gv, nullptr, gao, SS, CC, SS,
            (long)SS * SS, (long)SS * CC, (long)SS * CC);
        // proj + residual into x (reads attn-out directly via (B,H,S,C) perm)
        gemm_tc<128, false, false, true, false, true>
            <<<dim3(DD / 128, NBS / 128, 1), 256>>>(
            gao, proj_w + (size_t)l * DD * DD, nullptr, gx,
            NBS, DD, DD, 0, 0, 0);
        // ln2
        ln_kernel<<<NBS, 128>>>(gx, ln2_w + l * DD, ln2_b + l * DD, gln);
        // mlp fc1 + gelu
        gemm_tc<128, false, true, false, false, false>
            <<<dim3(MLPD / 128, NBS / 128, 1), 256>>>(
            gln, mlp_w1 + (size_t)l * MLPD * DD, mlp_b1 + l * MLPD, gmlp,
            NBS, MLPD, DD, 0, 0, 0);
        // mlp fc2 + bias + residual into x
        gemm_tc<128, false, false, true, false, false>
            <<<dim3(DD / 128, NBS / 128, 1), 256>>>(
            gmlp, mlp_w2 + (size_t)l * DD * MLPD, mlp_b2 + l * DD, gx,
            NBS, DD, MLPD, 0, 0, 0);
    }
    // final layernorm -> output
    ln_kernel<<<NBS, 128>>>(gx, lnf_w, lnf_b, out);
}

// round 8
// speedup vs baseline: 1.9200x; 1.0277x over previous
#include <cuda_runtime.h>
#include <cuda_bf16.h>
#include <math.h>

#define BB   4
#define SS   1024
#define DD   512
#define HH   8
#define CC   64
#define MLPD 2048
#define LL   4
#define TOPKK 256
#define D3   (3*DD)

typedef __nv_bfloat16 bf16;

// ---------------- scratch (static device globals) ---------------------------
__device__ float g_x  [BB*SS*DD];                  // residual stream (fp32)
__device__ float g_ln [BB*SS*DD];                  // as bf16 HL rows (B*S, 512H|512L)
__device__ float g_qkv[(size_t)BB*D3*SS];          // (B, 3D, S) fp32
__device__ float g_q  [BB*HH*SS*CC];               // bf16 HL rows (B*H*S, 64H|64L)
__device__ float g_k  [BB*HH*SS*CC];
__device__ float g_v  [BB*HH*SS*CC];               // bf16 HL rows (B*H*C, 1024H|1024L)  (transposed V)
__device__ float g_sc [(size_t)BB*HH*SS*SS];       // scores fp32 -> probs bf16 HL rows (1024H|1024L)
__device__ float g_ao [BB*SS*DD];                  // bf16 HL rows (B*S, 512H|512L)
__device__ float g_mlp[(size_t)BB*SS*MLPD];        // bf16 HL rows (B*S, 2048H|2048L)
// converted weights: [H block][L block]
__device__ bf16 c_qkv[(size_t)2*LL*D3*DD];
__device__ bf16 c_prj[(size_t)2*LL*DD*DD];
__device__ bf16 c_m1 [(size_t)2*LL*MLPD*DD];
__device__ bf16 c_m2 [(size_t)2*LL*DD*MLPD];

// ---------------- helpers ----------------
__device__ __forceinline__ float geluf(float x) {
    return 0.5f * x * (1.0f + erff(x * 0.70710678118654752440f));
}
__device__ __forceinline__ unsigned f2key(float f) {
    unsigned u = __float_as_uint(f);
    return (u & 0x80000000u) ? ~u : (u | 0x80000000u);
}
__device__ __forceinline__ float key2f(unsigned k) {
    unsigned u = (k & 0x80000000u) ? (k & 0x7FFFFFFFu) : ~k;
    return __uint_as_float(u);
}
__device__ __forceinline__ void splitw(float v, bf16& h, bf16& l) {
    h = __float2bfloat16_rn(v);
    l = __float2bfloat16_rn(v - __bfloat162float(h));
}
__device__ __forceinline__ void mma_bf16(float c[4], const unsigned a[4],
                                         const unsigned b[2]) {
    asm volatile(
        "mma.sync.aligned.m16n8k16.row.col.f32.bf16.bf16.f32 "
        "{%0,%1,%2,%3}, {%4,%5,%6,%7}, {%8,%9}, {%0,%1,%2,%3};"
        : "+f"(c[0]), "+f"(c[1]), "+f"(c[2]), "+f"(c[3])
        : "r"(a[0]), "r"(a[1]), "r"(a[2]), "r"(a[3]), "r"(b[0]), "r"(b[1]));
}
__device__ __forceinline__ void cp16(unsigned saddr, const void* g) {
    asm volatile("cp.async.cg.shared.global [%0], [%1], 16;\n" :: "r"(saddr), "l"(g));
}
__device__ __forceinline__ void ldm4(unsigned addr, unsigned& r0, unsigned& r1,
                                     unsigned& r2, unsigned& r3) {
    asm volatile("ldmatrix.sync.aligned.m8n8.x4.shared.b16 {%0,%1,%2,%3}, [%4];"
                 : "=r"(r0), "=r"(r1), "=r"(r2), "=r"(r3) : "r"(addr));
}

// ---------------- weight convert: fp32 -> bf16 hi/lo ------------------------
__global__ void conv_w(const float* __restrict__ s, bf16* __restrict__ dh,
                       bf16* __restrict__ dl, int n) {
    int i = blockIdx.x * 256 + threadIdx.x;
    if (i < n) {
        float x = s[i];
        bf16 h = __float2bfloat16_rn(x);
        dh[i] = h;
        dl[i] = __float2bfloat16_rn(x - __bfloat162float(h));
    }
}

// ---------------- x = x_in + pos ----------------
__global__ void add_pos_kernel(const float* __restrict__ x,
                               const float* __restrict__ pos,
                               float* __restrict__ out, int total, int per_b) {
    int i = blockIdx.x * blockDim.x + threadIdx.x;
    if (i < total) out[i] = x[i] + pos[i % per_b];
}

// ---------------- layernorm over D=512 --------------------------------------
template <bool BF16OUT>
__global__ void ln_kernel(const float* __restrict__ in,
                          const float* __restrict__ w,
                          const float* __restrict__ b,
                          void* __restrict__ outv) {
    int row = blockIdx.x;
    const float* xr = in + (size_t)row * DD;
    int tid = threadIdx.x;            // 128 threads
    float v[4], s = 0.f, sq = 0.f;
#pragma unroll
    for (int i = 0; i < 4; i++) {
        v[i] = xr[tid + i * 128];
        s += v[i]; sq += v[i] * v[i];
    }
    __shared__ float rs[32], rq[32];
#pragma unroll
    for (int o = 16; o; o >>= 1) {
        s  += __shfl_down_sync(0xFFFFFFFFu, s,  o);
        sq += __shfl_down_sync(0xFFFFFFFFu, sq, o);
    }
    int warp = tid >> 5, lane = tid & 31;
    if (lane == 0) { rs[warp] = s; rq[warp] = sq; }
    __syncthreads();
    if (tid == 0) {
        float a = 0.f, c = 0.f;
        for (int i = 0; i < 4; i++) { a += rs[i]; c += rq[i]; }
        rs[0] = a; rq[0] = c;
    }
    __syncthreads();
    float mu   = rs[0] * (1.0f / DD);
    float var  = rq[0] * (1.0f / DD) - mu * mu;
    float rstd = rsqrtf(var + 1e-6f);
    if (BF16OUT) {
        bf16* yr = (bf16*)outv + (size_t)row * (2 * DD);
#pragma unroll
        for (int i = 0; i < 4; i++) {
            int d = tid + i * 128;
            float y = (v[i] - mu) * rstd * w[d] + b[d];
            bf16 h, l; splitw(y, h, l);
            yr[d] = h; yr[DD + d] = l;
        }
    } else {
        float* yr = (float*)outv + (size_t)row * DD;
#pragma unroll
        for (int i = 0; i < 4; i++) {
            int d = tid + i * 128;
            yr[d] = (v[i] - mu) * rstd * w[d] + b[d];
        }
    }
}

// =================== pipelined bf16-split tensor-core GEMM ===================
// C(r,q) = sum_k X(r,k)*W(q,k); X rows: H at XH + r*ldx, L at XL + r*ldx.
// OUT_MODE: 0 = float Y (TRANS_OUT/RESID per flags)
//           1 = attn-out: bf16 HL into (B,S,D) rows (z = b*8+h)
//           2 = bf16 HL rows of width 2M (mlp1)
template <int QT, int OUT_MODE, bool TRANS_OUT, bool GELU_ACT, bool RESID>
__global__ void __launch_bounds__(256)
gemm_bf(const bf16* __restrict__ XHb, const bf16* __restrict__ XLb,
        const bf16* __restrict__ WHb, const bf16* __restrict__ WLb,
        const float* __restrict__ bias, void* __restrict__ Yv,
        int N, int M, int K, int ldx, int ldw, long xs, long ws, long ys) {
    constexpr int BK = 32;
    constexpr int LDBY = 80;                 // smem row stride (bytes): 64B data + 16B pad
    constexpr int XBYTES = 128 * LDBY;       // 10240
    constexpr int WBYTES = QT * LDBY;
    constexpr int STAGE  = 2 * XBYTES + 2 * WBYTES;
    constexpr int RW = (QT == 128) ? 64 : 32;
    constexpr int RTILES = RW / 16;

    extern __shared__ char smem_raw[];
    const unsigned sbase = (unsigned)__cvta_generic_to_shared(smem_raw);

    const bf16* XH = XHb + (size_t)blockIdx.z * xs;
    const bf16* XL = XLb + (size_t)blockIdx.z * xs;
    const bf16* WH = WHb + (size_t)blockIdx.z * ws;
    const bf16* WL = WLb + (size_t)blockIdx.z * ws;

    const int tid  = threadIdx.x;
    const int lane = tid & 31, warp = tid >> 5;
    const int wr = (QT == 128) ? (warp >> 2) : (warp >> 1);
    const int wq = (QT == 128) ? (warp & 3)  : (warp & 1);
    const int r_base = wr * RW, q_base = wq * 32;
    const int gr = lane >> 2, gc = lane & 3;
    const int lane15 = lane & 15;
    const int hi8 = (lane >> 4) & 1;

    const int q0 = blockIdx.x * QT, n0 = blockIdx.y * 128;
    const int nk = K / BK;

    // ldmatrix per-thread base offsets within a stage
    const unsigned aOff = (unsigned)((r_base + lane15) * LDBY + hi8 * 16);
    const unsigned bOff = (unsigned)(2 * XBYTES + (q_base + lane15) * LDBY + hi8 * 16);

    float acc[RTILES][4][4];
#pragma unroll
    for (int i = 0; i < RTILES; i++)
#pragma unroll
        for (int j = 0; j < 4; j++)
#pragma unroll
            for (int t = 0; t < 4; t++) acc[i][j][t] = 0.f;

    auto stage = [&](int it, int buf) {
        const int k0 = it * BK;
        const unsigned sb = sbase + buf * STAGE;
#pragma unroll
        for (int u = 0; u < 2; u++) {                 // X: 512 16B-chunks / array
            int c = tid + u * 256;
            int row = c >> 2, col = c & 3;
            size_t go = (size_t)(n0 + row) * ldx + k0 + col * 8;
            unsigned so = sb + row * LDBY + col * 16;
            cp16(so, XH + go);
            cp16(so + XBYTES, XL + go);
        }
#pragma unroll
        for (int u = 0; u < QT / 64; u++) {           // W: QT*4 chunks / array
            int c = tid + u * 256;
            int row = c >> 2, col = c & 3;
            size_t go = (size_t)(q0 + row) * ldw + k0 + col * 8;
            unsigned so = sb + 2 * XBYTES + row * LDBY + col * 16;
            cp16(so, WH + go);
            cp16(so + WBYTES, WL + go);
        }
        asm volatile("cp.async.commit_group;\n" ::);
    };

    stage(0, 0);
    for (int it = 0; it < nk; it++) {
        if (it + 1 < nk) {
            stage(it + 1, (it + 1) & 1);
            asm volatile("cp.async.wait_group 1;\n" ::);
        } else {
            asm volatile("cp.async.wait_group 0;\n" ::);
        }
        __syncthreads();
        const unsigned sb = sbase + (it & 1) * STAGE;
        const unsigned aH0 = sb + aOff;
        const unsigned bH0 = sb + bOff;
#pragma unroll
        for (int ks = 0; ks < BK; ks += 16) {
            unsigned aH[RTILES][4], aL[RTILES][4];
#pragma unroll
            for (int i = 0; i < RTILES; i++) {
                ldm4(aH0 + i * (16 * LDBY) + ks * 2,
                     aH[i][0], aH[i][1], aH[i][2], aH[i][3]);
                ldm4(aH0 + XBYTES + i * (16 * LDBY) + ks * 2,
                     aL[i][0], aL[i][1], aL[i][2], aL[i][3]);
            }
#pragma unroll
            for (int jp = 0; jp < 2; jp++) {
                unsigned bh[4], bl[4];
                ldm4(bH0 + jp * (16 * LDBY) + ks * 2, bh[0], bh[1], bh[2], bh[3]);
                ldm4(bH0 + WBYTES + jp * (16 * LDBY) + ks * 2,
                     bl[0], bl[1], bl[2], bl[3]);
#pragma unroll
                for (int jj = 0; jj < 2; jj++) {
                    const int j = 2 * jp + jj;
                    unsigned bHf[2] = { bh[jj], bh[2 + jj] };
                    unsigned bLf[2] = { bl[jj], bl[2 + jj] };
#pragma unroll
                    for (int i = 0; i < RTILES; i++) mma_bf16(acc[i][j], aH[i], bHf);
#pragma unroll
                    for (int i = 0; i < RTILES; i++) mma_bf16(acc[i][j], aH[i], bLf);
#pragma unroll
                    for (int i = 0; i < RTILES; i++) mma_bf16(acc[i][j], aL[i], bHf);
                }
            }
        }
        __syncthreads();
    }

    // ---- epilogue ----
#pragma unroll
    for (int i = 0; i < RTILES; i++) {
#pragma unroll
        for (int j = 0; j < 4; j++) {
#pragma unroll
            for (int t = 0; t < 4; t++) {
                int r = n0 + r_base + i * 16 + gr + ((t >= 2) ? 8 : 0);
                int q = q0 + q_base + j * 8 + 2 * gc + (t & 1);
                float v = acc[i][j][t];
                if (bias) v += bias[q];
                if (GELU_ACT) v = geluf(v);
                if (OUT_MODE == 0) {
                    float* Y = (float*)Yv + (size_t)blockIdx.z * ys;
                    size_t idx = TRANS_OUT ? ((size_t)q * N + r) : ((size_t)r * M + q);
                    if (RESID) Y[idx] += v; else Y[idx] = v;
                } else if (OUT_MODE == 1) {
                    bf16* Y = (bf16*)Yv;
                    int b = blockIdx.z >> 3, h = blockIdx.z & 7;
                    size_t base = ((size_t)(b * SS + r)) * 1024 + h * 64 + q;
                    bf16 hh, ll; splitw(v, hh, ll);
                    Y[base] = hh; Y[base + 512] = ll;
                } else {
                    bf16* Y = (bf16*)Yv;
                    size_t base = (size_t)r * (2 * MLPD) + q;
                    bf16 hh, ll; splitw(v, hh, ll);
                    Y[base] = hh; Y[base + MLPD] = ll;
                }
            }
        }
    }
}

// ------- depthwise conv3 + head split + (q,k) L2-normalize -------------------
// q/k out: bf16 HL rows (B,H,S): [c]=H, [64+c]=L.  v out: transposed bf16 HL
// rows (B,H,C): [s]=H, [1024+s]=L.
__global__ void conv_heads(const float* __restrict__ qkv,
                           const float* __restrict__ dw,  // (3D, 3)
                           bf16* __restrict__ q,
                           bf16* __restrict__ k,
                           bf16* __restrict__ v) {
    int b = blockIdx.z;
    int part = blockIdx.y / HH, h = blockIdx.y % HH;
    int s0 = blockIdx.x * 64;
    int ch0 = part * DD + h * CC;
    __shared__ float tin[64][66];
    __shared__ float ct[64][65];
    int tid = threadIdx.x;

    for (int idx = tid; idx < 64 * 66; idx += 256) {
        int c = idx / 66, j = idx % 66;
        int s = s0 + j - 1;
        float val = 0.f;
        if (s >= 0 && s < SS) val = qkv[((size_t)b * D3 + ch0 + c) * SS + s];
        tin[c][j] = val;
    }
    __syncthreads();
    for (int idx = tid; idx < 4096; idx += 256) {
        int c = idx >> 6, s = idx & 63;
        const float* wp = dw + (ch0 + c) * 3;
        ct[c][s] = wp[0] * tin[c][s] + wp[1] * tin[c][s + 1] + wp[2] * tin[c][s + 2];
    }
    __syncthreads();
    if (part == 2) {
        bf16* outv = v + ((size_t)(b * HH + h) * CC) * 2048;
        for (int idx = tid; idx < 4096; idx += 256) {
            int s = idx >> 6, c = idx & 63;
            bf16 hh, ll; splitw(ct[c][s], hh, ll);
            outv[(size_t)c * 2048 + s0 + s] = hh;
            outv[(size_t)c * 2048 + 1024 + s0 + s] = ll;
        }
    } else {
        __shared__ float red[4][64];
        __shared__ float rnorm[64];
        int tx = tid & 63, ty = tid >> 6;
        float p = 0.f;
        for (int c = ty * 16; c < ty * 16 + 16; c++) {
            float u = ct[c][tx];
            p += u * u;
        }
        red[ty][tx] = p;
        __syncthreads();
        if (ty == 0) {
            float nn = red[0][tx] + red[1][tx] + red[2][tx] + red[3][tx];
            rnorm[tx] = 1.f / fmaxf(sqrtf(nn), 1e-12f);
        }
        __syncthreads();
        bf16* out = (part == 0 ? q : k) + ((size_t)(b * HH + h) * SS + s0) * 128;
        for (int idx = tid; idx < 4096; idx += 256) {
            int s = idx >> 6, c = idx & 63;
            bf16 hh, ll; splitw(ct[c][s] * rnorm[s], hh, ll);
            out[s * 128 + c] = hh;
            out[s * 128 + 64 + c] = ll;
        }
    }
}

// ------- top-k (exact radix select) + masked softmax -------------------------
// reads fp32 scores row, writes probs bf16 HL in place (row: 1024 H | 1024 L).
__global__ void topk_softmax(float* __restrict__ scores,
                             const float* __restrict__ temp) {
    int bh = blockIdx.y;
    int h = bh % HH;
    int s = blockIdx.x;
    float* row = scores + ((size_t)bh * SS + s) * SS;
    float t = temp[h];
    __shared__ unsigned keys[SS];
    __shared__ unsigned hist[256];
    __shared__ unsigned sfx[256];
    __shared__ float fred[256];
    __shared__ unsigned sh_prefix;
    __shared__ int sh_k;
    int tid = threadIdx.x;

    float lmax = -3.4e38f;
#pragma unroll
    for (int i = 0; i < 4; i++) {
        int idx = tid + i * 256;
        float f = row[idx] * t;
        keys[idx] = f2key(f);
        lmax = fmaxf(lmax, f);
    }
    fred[tid] = lmax;
    __syncthreads();
    for (int o = 128; o; o >>= 1) {
        if (tid < o) fred[tid] = fmaxf(fred[tid], fred[tid + o]);
        __syncthreads();
    }
    float maxv = fred[0];
    if (tid == 0) { sh_prefix = 0u; sh_k = TOPKK; }
    __syncthreads();

    for (int pass = 0; pass < 4; pass++) {
        int shift = 24 - 8 * pass;
        hist[tid] = 0u;
        __syncthreads();
        unsigned pref = sh_prefix;
        int kk = sh_k;
        unsigned mask = (pass == 0) ? 0u : (0xFFFFFFFFu << (shift + 8));
#pragma unroll
        for (int i = 0; i < 4; i++) {
            unsigned key = keys[tid + i * 256];
            if ((key & mask) == pref) atomicAdd(&hist[(key >> shift) & 255], 1u);
        }
        __syncthreads();
        sfx[tid] = hist[tid];
        __syncthreads();
        for (int o = 1; o < 256; o <<= 1) {
            unsigned v = sfx[tid];
            unsigned add = (tid + o < 256) ? sfx[tid + o] : 0u;
            __syncthreads();
            sfx[tid] = v + add;
            __syncthreads();
        }
        int above = (tid == 255) ? 0 : (int)sfx[tid + 1];
        if ((int)sfx[tid] >= kk && above < kk) {
            sh_prefix = pref | ((unsigned)tid << shift);
            sh_k = kk - above;
        }
        __syncthreads();
    }
    float vstar = key2f(sh_prefix);
    float m = fminf(fmaxf(maxv, -10000.f), 10000.f);

    float lsum = 0.f;
#pragma unroll
    for (int i = 0; i < 4; i++) {
        int idx = tid + i * 256;
        float f = key2f(keys[idx]);
        float p = (f >= vstar) ? fminf(fmaxf(f, -10000.f), 10000.f) : -10000.f;
        float e = expf(p - m);
        ((float*)keys)[idx] = e;
        lsum += e;
    }
    fred[tid] = lsum;
    __syncthreads();
    for (int o = 128; o; o >>= 1) {
        if (tid < o) fred[tid] += fred[tid + o];
        __syncthreads();
    }
    float inv = 1.f / fred[0];
    bf16* brow = (bf16*)row;
#pragma unroll
    for (int i = 0; i < 4; i++) {
        int idx = tid + i * 256;
        bf16 hh, ll; splitw(((float*)keys)[idx] * inv, hh, ll);
        brow[idx] = hh;
        brow[1024 + idx] = ll;
    }
}

// ---------------- host orchestration ----------------------------------------
extern "C" void kernel_launch(void* const* d_in, const int* in_sizes, int n_in,
                              void* d_out, int out_size) {
    (void)in_sizes; (void)n_in; (void)out_size;
    const float* x      = (const float*)d_in[0];
    const float* pos    = (const float*)d_in[1];
    const float* ln1_w  = (const float*)d_in[2];
    const float* ln1_b  = (const float*)d_in[3];
    const float* qkv_w  = (const float*)d_in[4];
    const float* dw_w   = (const float*)d_in[5];
    const float* temp   = (const float*)d_in[6];
    const float* proj_w = (const float*)d_in[7];
    const float* ln2_w  = (const float*)d_in[8];
    const float* ln2_b  = (const float*)d_in[9];
    const float* mlp_w1 = (const float*)d_in[10];
    const float* mlp_b1 = (const float*)d_in[11];
    const float* mlp_w2 = (const float*)d_in[12];
    const float* mlp_b2 = (const float*)d_in[13];
    const float* lnf_w  = (const float*)d_in[14];
    const float* lnf_b  = (const float*)d_in[15];
    float* out = (float*)d_out;

    float *gx, *gln, *gqkv, *gq, *gk, *gv, *gsc, *gao, *gmlp;
    bf16 *cqkv, *cprj, *cm1, *cm2;
    cudaGetSymbolAddress((void**)&gx,   g_x);
    cudaGetSymbolAddress((void**)&gln,  g_ln);
    cudaGetSymbolAddress((void**)&gqkv, g_qkv);
    cudaGetSymbolAddress((void**)&gq,   g_q);
    cudaGetSymbolAddress((void**)&gk,   g_k);
    cudaGetSymbolAddress((void**)&gv,   g_v);
    cudaGetSymbolAddress((void**)&gsc,  g_sc);
    cudaGetSymbolAddress((void**)&gao,  g_ao);
    cudaGetSymbolAddress((void**)&gmlp, g_mlp);
    cudaGetSymbolAddress((void**)&cqkv, c_qkv);
    cudaGetSymbolAddress((void**)&cprj, c_prj);
    cudaGetSymbolAddress((void**)&cm1,  c_m1);
    cudaGetSymbolAddress((void**)&cm2,  c_m2);

    // dynamic smem opt-in (QT=128: 81920B; QT=64: 61440B)
    cudaFuncSetAttribute(gemm_bf<128, 0, true,  false, false>,
                         cudaFuncAttributeMaxDynamicSharedMemorySize, 81920);
    cudaFuncSetAttribute(gemm_bf<128, 0, false, false, false>,
                         cudaFuncAttributeMaxDynamicSharedMemorySize, 81920);
    cudaFuncSetAttribute(gemm_bf<128, 0, false, false, true>,
                         cudaFuncAttributeMaxDynamicSharedMemorySize, 81920);
    cudaFuncSetAttribute(gemm_bf<128, 2, false, true,  false>,
                         cudaFuncAttributeMaxDynamicSharedMemorySize, 81920);
    cudaFuncSetAttribute(gemm_bf<64,  1, false, false, false>,
                         cudaFuncAttributeMaxDynamicSharedMemorySize, 61440);

    // convert weights once per call (cheap, deterministic)
    {
        int n;
        n = LL * D3 * DD;
        conv_w<<<(n + 255) / 256, 256>>>(qkv_w,  cqkv, cqkv + n, n);
        n = LL * DD * DD;
        conv_w<<<(n + 255) / 256, 256>>>(proj_w, cprj, cprj + n, n);
        n = LL * MLPD * DD;
        conv_w<<<(n + 255) / 256, 256>>>(mlp_w1, cm1, cm1 + n, n);
        n = LL * DD * MLPD;
        conv_w<<<(n + 255) / 256, 256>>>(mlp_w2, cm2, cm2 + n, n);
    }

    const int NBS = BB * SS;           // 4096 rows
    add_pos_kernel<<<(BB * SS * DD + 255) / 256, 256>>>(x, pos, gx,
                                                        BB * SS * DD, SS * DD);

    const bf16* lnH = (const bf16*)gln;
    const bf16* qH  = (const bf16*)gq;
    const bf16* kH  = (const bf16*)gk;
    const bf16* vH  = (const bf16*)gv;
    const bf16* pH  = (const bf16*)gsc;
    const bf16* aoH = (const bf16*)gao;
    const bf16* mH  = (const bf16*)gmlp;

    for (int l = 0; l < LL; l++) {
        // ln1 -> bf16 HL
        ln_kernel<true><<<NBS, 128>>>(gx, ln1_w + l * DD, ln1_b + l * DD, gln);
        // qkv: per batch (1536 x 512) @ (512 x 1024)^T -> (B, 3D, S) fp32
        {
            const bf16* wh = cqkv + (size_t)l * D3 * DD;
            const bf16* wl = wh + (size_t)LL * D3 * DD;
            gemm_bf<128, 0, true, false, false>
                <<<dim3(D3 / 128, SS / 128, BB), 256, 81920>>>(
                lnH, lnH + DD, wh, wl, nullptr, gqkv,
                SS, D3, DD, 2 * DD, DD, (long)SS * 2 * DD, 0, (long)D3 * SS);
        }
        // depthwise conv3 + head split + q/k normalize (bf16 HL out)
        conv_heads<<<dim3(SS / 64, 3 * HH, BB), 256>>>(
            gqkv, dw_w + (size_t)l * D3 * 3, (bf16*)gq, (bf16*)gk, (bf16*)gv);
        // scores = q k^T (K=64) -> fp32
        gemm_bf<128, 0, false, false, false>
            <<<dim3(SS / 128, SS / 128, BB * HH), 256, 81920>>>(
            qH, qH + 64, kH, kH + 64, nullptr, gsc,
            SS, SS, CC, 128, 128, (long)SS * 128, (long)SS * 128, (long)SS * SS);
        // top-k + masked softmax -> probs bf16 HL (in place)
        topk_softmax<<<dim3(SS, BB * HH), 256>>>(gsc, temp + l * HH);
        // attn @ V -> gao bf16 HL in (B,S,D) layout
        gemm_bf<64, 1, false, false, false>
            <<<dim3(1, SS / 128, BB * HH), 256, 61440>>>(
            pH, pH + 1024, vH, vH + 1024, nullptr, gao,
            SS, CC, SS, 2 * SS, 2 * SS, (long)SS * 2 * SS, (long)CC * 2 * SS, 0);
        // proj + residual into x (fp32)
        {
            const bf16* wh = cprj + (size_t)l * DD * DD;
            const bf16* wl = wh + (size_t)LL * DD * DD;
            gemm_bf<128, 0, false, false, true>
                <<<dim3(DD / 128, NBS / 128, 1), 256, 81920>>>(
                aoH, aoH + DD, wh, wl, nullptr, gx,
                NBS, DD, DD, 2 * DD, DD, 0, 0, 0);
        }
        // ln2 -> bf16 HL
        ln_kernel<true><<<NBS, 128>>>(gx, ln2_w + l * DD, ln2_b + l * DD, gln);
        // mlp fc1 + gelu -> gmlp bf16 HL
        {
            const bf16* wh = cm1 + (size_t)l * MLPD * DD;
            const bf16* wl = wh + (size_t)LL * MLPD * DD;
            gemm_bf<128, 2, false, true, false>
                <<<dim3(MLPD / 128, NBS / 128, 1), 256, 81920>>>(
                lnH, lnH + DD, wh, wl, mlp_b1 + l * MLPD, gmlp,
                NBS, MLPD, DD, 2 * DD, DD, 0, 0, 0);
        }
        // mlp fc2 + bias + residual into x (fp32)
        {
            const bf16* wh = cm2 + (size_t)l * DD * MLPD;
            const bf16* wl = wh + (size_t)LL * DD * MLPD;
            gemm_bf<128, 0, false, false, true>
                <<<dim3(DD / 128, NBS / 128, 1), 256, 81920>>>(
                mH, mH + MLPD, wh, wl, mlp_b2 + l * DD, gx,
                NBS, DD, MLPD, 2 * MLPD, MLPD, 0, 0, 0);
        }
    }
    // final layernorm -> fp32 output
    ln_kernel<false><<<NBS, 128>>>(gx, lnf_w, lnf_b, out);
}

// round 15
// speedup vs baseline: 2.8955x; 1.5080x over previous
#include <cuda_runtime.h>
#include <cuda_fp16.h>
#include <cstdint>
#include <math.h>

#define BB   4
#define SS   1024
#define DD   512
#define HH   8
#define CC   64
#define MLPD 2048
#define LL   4
#define TOPKK 256
#define D3   (3*DD)

// ---------------- scratch (static device globals) ---------------------------
__device__ float g_x  [BB*SS*DD];                  // residual stream (fp32)
__device__ half  g_ln [BB*SS*DD];                  // fp16 rows (B*S, 512)
__device__ float g_qkv[(size_t)BB*D3*SS];          // (B, 3D, S) fp32
__device__ half  g_q  [BB*HH*SS*CC];               // fp16 rows (B*H*S, 64)
__device__ half  g_k  [BB*HH*SS*CC];
__device__ half  g_v  [BB*HH*CC*SS];               // fp16 transposed rows (B*H*C, 1024)
__device__ float g_sc [(size_t)BB*HH*SS*SS];       // scores fp32 -> probs fp16 (row pitch 2*SS halves)
__device__ half  g_ao [BB*SS*DD];                  // fp16 rows (B*S, 512)
__device__ half  g_mlp[(size_t)BB*SS*MLPD];        // fp16 rows (B*S, 2048)
__device__ half  c_qkv[(size_t)LL*D3*DD];
__device__ half  c_prj[(size_t)LL*DD*DD];
__device__ half  c_m1 [(size_t)LL*MLPD*DD];
__device__ half  c_m2 [(size_t)LL*DD*MLPD];

// ---------------- helpers ----------------
__device__ __forceinline__ float geluf(float x) {
    return 0.5f * x * (1.0f + erff(x * 0.70710678118654752440f));
}
__device__ __forceinline__ unsigned f2key(float f) {
    unsigned u = __float_as_uint(f);
    return (u & 0x80000000u) ? ~u : (u | 0x80000000u);
}
__device__ __forceinline__ float key2f(unsigned k) {
    unsigned u = (k & 0x80000000u) ? (k & 0x7FFFFFFFu) : ~k;
    return __uint_as_float(u);
}
// fp16 mma: D(f32) += A(16x16 f16, row) * B(16x8 f16, col)
__device__ __forceinline__ void mma_hf(float c[4], const unsigned a[4],
                                       const unsigned b[2]) {
    asm volatile(
        "mma.sync.aligned.m16n8k16.row.col.f32.f16.f16.f32 "
        "{%0,%1,%2,%3}, {%4,%5,%6,%7}, {%8,%9}, {%0,%1,%2,%3};"
        : "+f"(c[0]), "+f"(c[1]), "+f"(c[2]), "+f"(c[3])
        : "r"(a[0]), "r"(a[1]), "r"(a[2]), "r"(a[3]), "r"(b[0]), "r"(b[1]));
}
__device__ __forceinline__ void cp16(unsigned saddr, const void* g) {
    asm volatile("cp.async.cg.shared.global [%0], [%1], 16;\n" :: "r"(saddr), "l"(g));
}
__device__ __forceinline__ void ldm4(unsigned addr, unsigned& r0, unsigned& r1,
                                     unsigned& r2, unsigned& r3) {
    asm volatile("ldmatrix.sync.aligned.m8n8.x4.shared.b16 {%0,%1,%2,%3}, [%4];"
                 : "=r"(r0), "=r"(r1), "=r"(r2), "=r"(r3) : "r"(addr));
}

// ---------------- weight convert: fp32 -> fp16 -------------------------------
__global__ void conv_w(const float* __restrict__ s, half* __restrict__ d, int n) {
    int i = blockIdx.x * 256 + threadIdx.x;
    if (i < n) d[i] = __float2half_rn(s[i]);
}

// ---------------- x = x_in + pos ----------------
__global__ void add_pos_kernel(const float* __restrict__ x,
                               const float* __restrict__ pos,
                               float* __restrict__ out, int total, int per_b) {
    int i = blockIdx.x * blockDim.x + threadIdx.x;
    if (i < total) out[i] = x[i] + pos[i % per_b];
}

// ---------------- layernorm over D=512 --------------------------------------
template <bool HF16OUT>
__global__ void ln_kernel(const float* __restrict__ in,
                          const float* __restrict__ w,
                          const float* __restrict__ b,
                          void* __restrict__ outv) {
    int row = blockIdx.x;
    const float* xr = in + (size_t)row * DD;
    int tid = threadIdx.x;            // 128 threads
    float v[4], s = 0.f, sq = 0.f;
#pragma unroll
    for (int i = 0; i < 4; i++) {
        v[i] = xr[tid + i * 128];
        s += v[i]; sq += v[i] * v[i];
    }
    __shared__ float rs[32], rq[32];
#pragma unroll
    for (int o = 16; o; o >>= 1) {
        s  += __shfl_down_sync(0xFFFFFFFFu, s,  o);
        sq += __shfl_down_sync(0xFFFFFFFFu, sq, o);
    }
    int warp = tid >> 5, lane = tid & 31;
    if (lane == 0) { rs[warp] = s; rq[warp] = sq; }
    __syncthreads();
    if (tid == 0) {
        float a = 0.f, c = 0.f;
        for (int i = 0; i < 4; i++) { a += rs[i]; c += rq[i]; }
        rs[0] = a; rq[0] = c;
    }
    __syncthreads();
    float mu   = rs[0] * (1.0f / DD);
    float var  = rq[0] * (1.0f / DD) - mu * mu;
    float rstd = rsqrtf(var + 1e-6f);
    if (HF16OUT) {
        half* yr = (half*)outv + (size_t)row * DD;
#pragma unroll
        for (int i = 0; i < 4; i++) {
            int d = tid + i * 128;
            yr[d] = __float2half_rn((v[i] - mu) * rstd * w[d] + b[d]);
        }
    } else {
        float* yr = (float*)outv + (size_t)row * DD;
#pragma unroll
        for (int i = 0; i < 4; i++) {
            int d = tid + i * 128;
            yr[d] = (v[i] - mu) * rstd * w[d] + b[d];
        }
    }
}

// =================== pipelined single-pass fp16 tensor-core GEMM =============
// C(r,q) = sum_k X(r,k)*W(q,k); X rows at X + r*ldx, W rows at W + q*ldw.
// Block tile: 128(r) x QT(q), BK=32.  8 warps of (RW x 32). fp32 accum.
// OUT_MODE: 0 = float Y (TRANS_OUT/RESID per flags)
//           1 = attn-out: fp16 into (B,S,D) rows (z = b*8+h)
//           2 = fp16 rows of width M (mlp1)
template <int QT, int OUT_MODE, bool TRANS_OUT, bool GELU_ACT, bool RESID>
__global__ void __launch_bounds__(256)
gemm_hf(const half* __restrict__ Xb, const half* __restrict__ Wb,
        const float* __restrict__ bias, void* __restrict__ Yv,
        int N, int M, int K, int ldx, int ldw, long xs, long ws, long ys) {
    constexpr int BK  = 32;
    constexpr int LDBY = 80;                 // smem row stride: 64B data + 16B pad
    constexpr int XBYTES = 128 * LDBY;       // 10240
    constexpr int WBYTES = QT * LDBY;
    constexpr int STAGE  = XBYTES + WBYTES;
    constexpr int RW = (QT == 128) ? 64 : 32;
    constexpr int RTILES = RW / 16;

    extern __shared__ char smem_raw[];
    const unsigned sbase = (unsigned)__cvta_generic_to_shared(smem_raw);

    const half* X = Xb + (size_t)blockIdx.z * xs;
    const half* W = Wb + (size_t)blockIdx.z * ws;

    const int tid  = threadIdx.x;
    const int lane = tid & 31, warp = tid >> 5;
    const int wr = (QT == 128) ? (warp >> 2) : (warp >> 1);
    const int wq = (QT == 128) ? (warp & 3)  : (warp & 1);
    const int r_base = wr * RW, q_base = wq * 32;
    const int gr = lane >> 2, gc = lane & 3;
    const int lane15 = lane & 15;
    const int hi8 = (lane >> 4) & 1;

    const int q0 = blockIdx.x * QT, n0 = blockIdx.y * 128;
    const int nk = K / BK;

    const unsigned aOff = (unsigned)((r_base + lane15) * LDBY + hi8 * 16);
    const unsigned bOff = (unsigned)(XBYTES + (q_base + lane15) * LDBY + hi8 * 16);

    float acc[RTILES][4][4];
#pragma unroll
    for (int i = 0; i < RTILES; i++)
#pragma unroll
        for (int j = 0; j < 4; j++)
#pragma unroll
            for (int t = 0; t < 4; t++) acc[i][j][t] = 0.f;

    auto stage = [&](int it, int buf) {
        const int k0 = it * BK;
        const unsigned sb = sbase + buf * STAGE;
#pragma unroll
        for (int u = 0; u < 2; u++) {                 // X: 512 16B-chunks
            int c = tid + u * 256;
            int row = c >> 2, col = c & 3;
            cp16(sb + row * LDBY + col * 16,
                 X + (size_t)(n0 + row) * ldx + k0 + col * 8);
        }
#pragma unroll
        for (int u = 0; u < QT / 64; u++) {           // W: QT*4 chunks
            int c = tid + u * 256;
            int row = c >> 2, col = c & 3;
            cp16(sb + XBYTES + row * LDBY + col * 16,
                 W + (size_t)(q0 + row) * ldw + k0 + col * 8);
        }
        asm volatile("cp.async.commit_group;\n" ::);
    };

    stage(0, 0);
    for (int it = 0; it < nk; it++) {
        if (it + 1 < nk) {
            stage(it + 1, (it + 1) & 1);
            asm volatile("cp.async.wait_group 1;\n" ::);
        } else {
            asm volatile("cp.async.wait_group 0;\n" ::);
        }
        __syncthreads();
        const unsigned sb = sbase + (it & 1) * STAGE;
        const unsigned aH0 = sb + aOff;
        const unsigned bH0 = sb + bOff;
#pragma unroll
        for (int ks = 0; ks < BK; ks += 16) {
            unsigned a[RTILES][4];
#pragma unroll
            for (int i = 0; i < RTILES; i++) {
                ldm4(aH0 + i * (16 * LDBY) + ks * 2,
                     a[i][0], a[i][1], a[i][2], a[i][3]);
            }
#pragma unroll
            for (int jp = 0; jp < 2; jp++) {
                unsigned bb[4];
                ldm4(bH0 + jp * (16 * LDBY) + ks * 2, bb[0], bb[1], bb[2], bb[3]);
#pragma unroll
                for (int jj = 0; jj < 2; jj++) {
                    const int j = 2 * jp + jj;
                    unsigned bf[2] = { bb[jj], bb[2 + jj] };
#pragma unroll
                    for (int i = 0; i < RTILES; i++) mma_hf(acc[i][j], a[i], bf);
                }
            }
        }
        __syncthreads();
    }

    // ---- epilogue ----
#pragma unroll
    for (int i = 0; i < RTILES; i++) {
#pragma unroll
        for (int j = 0; j < 4; j++) {
#pragma unroll
            for (int t = 0; t < 4; t++) {
                int r = n0 + r_base + i * 16 + gr + ((t >= 2) ? 8 : 0);
                int q = q0 + q_base + j * 8 + 2 * gc + (t & 1);
                float v = acc[i][j][t];
                if (bias) v += bias[q];
                if (GELU_ACT) v = geluf(v);
                if (OUT_MODE == 0) {
                    float* Y = (float*)Yv + (size_t)blockIdx.z * ys;
                    size_t idx = TRANS_OUT ? ((size_t)q * N + r) : ((size_t)r * M + q);
                    if (RESID) Y[idx] += v; else Y[idx] = v;
                } else if (OUT_MODE == 1) {
                    half* Y = (half*)Yv;
                    int b = blockIdx.z >> 3, h = blockIdx.z & 7;
                    Y[((size_t)(b * SS + r)) * DD + h * CC + q] = __float2half_rn(v);
                } else {
                    half* Y = (half*)Yv;
                    Y[(size_t)r * MLPD + q] = __float2half_rn(v);
                }
            }
        }
    }
}

// ------- depthwise conv3 + head split + (q,k) L2-normalize -------------------
// q/k out: fp16 rows (B,H,S) width 64.  v out: fp16 transposed rows (B,H,C)
// width 1024.
__global__ void conv_heads(const float* __restrict__ qkv,
                           const float* __restrict__ dw,  // (3D, 3)
                           half* __restrict__ q,
                           half* __restrict__ k,
                           half* __restrict__ v) {
    int b = blockIdx.z;
    int part = blockIdx.y / HH, h = blockIdx.y % HH;
    int s0 = blockIdx.x * 64;
    int ch0 = part * DD + h * CC;
    __shared__ float tin[64][66];
    __shared__ float ct[64][65];
    int tid = threadIdx.x;

    for (int idx = tid; idx < 64 * 66; idx += 256) {
        int c = idx / 66, j = idx % 66;
        int s = s0 + j - 1;
        float val = 0.f;
        if (s >= 0 && s < SS) val = qkv[((size_t)b * D3 + ch0 + c) * SS + s];
        tin[c][j] = val;
    }
    __syncthreads();
    for (int idx = tid; idx < 4096; idx += 256) {
        int c = idx >> 6, s = idx & 63;
        const float* wp = dw + (ch0 + c) * 3;
        ct[c][s] = wp[0] * tin[c][s] + wp[1] * tin[c][s + 1] + wp[2] * tin[c][s + 2];
    }
    __syncthreads();
    if (part == 2) {
        half* outv = v + ((size_t)(b * HH + h) * CC) * SS;
        for (int idx = tid; idx < 4096; idx += 256) {
            int s = idx >> 6, c = idx & 63;
            outv[(size_t)c * SS + s0 + s] = __float2half_rn(ct[c][s]);
        }
    } else {
        __shared__ float red[4][64];
        __shared__ float rnorm[64];
        int tx = tid & 63, ty = tid >> 6;
        float p = 0.f;
        for (int c = ty * 16; c < ty * 16 + 16; c++) {
            float u = ct[c][tx];
            p += u * u;
        }
        red[ty][tx] = p;
        __syncthreads();
        if (ty == 0) {
            float nn = red[0][tx] + red[1][tx] + red[2][tx] + red[3][tx];
            rnorm[tx] = 1.f / fmaxf(sqrtf(nn), 1e-12f);
        }
        __syncthreads();
        half* out = (part == 0 ? q : k) + ((size_t)(b * HH + h) * SS + s0) * CC;
        for (int idx = tid; idx < 4096; idx += 256) {
            int s = idx >> 6, c = idx & 63;
            out[s * CC + c] = __float2half_rn(ct[c][s] * rnorm[s]);
        }
    }
}

// ------- top-k (exact radix select) + masked softmax -------------------------
// reads fp32 scores row, writes probs fp16 into first half of the row
// (fp16 row pitch = 2*SS halves = the fp32 row pitch).
__global__ void topk_softmax(float* __restrict__ scores,
                             const float* __restrict__ temp) {
    int bh = blockIdx.y;
    int h = bh % HH;
    int s = blockIdx.x;
    float* row = scores + ((size_t)bh * SS + s) * SS;
    float t = temp[h];
    __shared__ unsigned keys[SS];
    __shared__ unsigned hist[256];
    __shared__ unsigned sfx[256];
    __shared__ float fred[256];
    __shared__ unsigned sh_prefix;
    __shared__ int sh_k;
    int tid = threadIdx.x;

    float lmax = -3.4e38f;
#pragma unroll
    for (int i = 0; i < 4; i++) {
        int idx = tid + i * 256;
        float f = row[idx] * t;
        keys[idx] = f2key(f);
        lmax = fmaxf(lmax, f);
    }
    fred[tid] = lmax;
    __syncthreads();
    for (int o = 128; o; o >>= 1) {
        if (tid < o) fred[tid] = fmaxf(fred[tid], fred[tid + o]);
        __syncthreads();
    }
    float maxv = fred[0];
    if (tid == 0) { sh_prefix = 0u; sh_k = TOPKK; }
    __syncthreads();

    for (int pass = 0; pass < 4; pass++) {
        int shift = 24 - 8 * pass;
        hist[tid] = 0u;
        __syncthreads();
        unsigned pref = sh_prefix;
        int kk = sh_k;
        unsigned mask = (pass == 0) ? 0u : (0xFFFFFFFFu << (shift + 8));
#pragma unroll
        for (int i = 0; i < 4; i++) {
            unsigned key = keys[tid + i * 256];
            if ((key & mask) == pref) atomicAdd(&hist[(key >> shift) & 255], 1u);
        }
        __syncthreads();
        sfx[tid] = hist[tid];
        __syncthreads();
        for (int o = 1; o < 256; o <<= 1) {
            unsigned v = sfx[tid];
            unsigned add = (tid + o < 256) ? sfx[tid + o] : 0u;
            __syncthreads();
            sfx[tid] = v + add;
            __syncthreads();
        }
        int above = (tid == 255) ? 0 : (int)sfx[tid + 1];
        if ((int)sfx[tid] >= kk && above < kk) {
            sh_prefix = pref | ((unsigned)tid << shift);
            sh_k = kk - above;
        }
        __syncthreads();
    }
    float vstar = key2f(sh_prefix);
    float m = fminf(fmaxf(maxv, -10000.f), 10000.f);

    float lsum = 0.f;
#pragma unroll
    for (int i = 0; i < 4; i++) {
        int idx = tid + i * 256;
        float f = key2f(keys[idx]);
        float p = (f >= vstar) ? fminf(fmaxf(f, -10000.f), 10000.f) : -10000.f;
        float e = expf(p - m);
        ((float*)keys)[idx] = e;
        lsum += e;
    }
    fred[tid] = lsum;
    __syncthreads();
    for (int o = 128; o; o >>= 1) {
        if (tid < o) fred[tid] += fred[tid + o];
        __syncthreads();
    }
    float inv = 1.f / fred[0];
    half* hrow = (half*)row;
#pragma unroll
    for (int i = 0; i < 4; i++) {
        int idx = tid + i * 256;
        hrow[idx] = __float2half_rn(((float*)keys)[idx] * inv);
    }
}

// ---------------- host orchestration ----------------------------------------
extern "C" void kernel_launch(void* const* d_in, const int* in_sizes, int n_in,
                              void* d_out, int out_size) {
    (void)in_sizes; (void)n_in; (void)out_size;
    const float* x      = (const float*)d_in[0];
    const float* pos    = (const float*)d_in[1];
    const float* ln1_w  = (const float*)d_in[2];
    const float* ln1_b  = (const float*)d_in[3];
    const float* qkv_w  = (const float*)d_in[4];
    const float* dw_w   = (const float*)d_in[5];
    const float* temp   = (const float*)d_in[6];
    const float* proj_w = (const float*)d_in[7];
    const float* ln2_w  = (const float*)d_in[8];
    const float* ln2_b  = (const float*)d_in[9];
    const float* mlp_w1 = (const float*)d_in[10];
    const float* mlp_b1 = (const float*)d_in[11];
    const float* mlp_w2 = (const float*)d_in[12];
    const float* mlp_b2 = (const float*)d_in[13];
    const float* lnf_w  = (const float*)d_in[14];
    const float* lnf_b  = (const float*)d_in[15];
    float* out = (float*)d_out;

    float *gx, *gqkv, *gsc;
    half *gln, *gq, *gk, *gv, *gao, *gmlp;
    half *cqkv, *cprj, *cm1, *cm2;
    cudaGetSymbolAddress((void**)&gx,   g_x);
    cudaGetSymbolAddress((void**)&gln,  g_ln);
    cudaGetSymbolAddress((void**)&gqkv, g_qkv);
    cudaGetSymbolAddress((void**)&gq,   g_q);
    cudaGetSymbolAddress((void**)&gk,   g_k);
    cudaGetSymbolAddress((void**)&gv,   g_v);
    cudaGetSymbolAddress((void**)&gsc,  g_sc);
    cudaGetSymbolAddress((void**)&gao,  g_ao);
    cudaGetSymbolAddress((void**)&gmlp, g_mlp);
    cudaGetSymbolAddress((void**)&cqkv, c_qkv);
    cudaGetSymbolAddress((void**)&cprj, c_prj);
    cudaGetSymbolAddress((void**)&cm1,  c_m1);
    cudaGetSymbolAddress((void**)&cm2,  c_m2);

    const int SM128 = (128 * 80 + 128 * 80) * 2;   // 40960
    const int SM64  = (128 * 80 + 64 * 80) * 2;    // 30720

    {
        int n;
        n = LL * D3 * DD;
        conv_w<<<(n + 255) / 256, 256>>>(qkv_w,  cqkv, n);
        n = LL * DD * DD;
        conv_w<<<(n + 255) / 256, 256>>>(proj_w, cprj, n);
        n = LL * MLPD * DD;
        conv_w<<<(n + 255) / 256, 256>>>(mlp_w1, cm1, n);
        n = LL * DD * MLPD;
        conv_w<<<(n + 255) / 256, 256>>>(mlp_w2, cm2, n);
    }

    const int NBS = BB * SS;
    add_pos_kernel<<<(BB * SS * DD + 255) / 256, 256>>>(x, pos, gx,
                                                        BB * SS * DD, SS * DD);

    for (int l = 0; l < LL; l++) {
        ln_kernel<true><<<NBS, 128>>>(gx, ln1_w + l * DD, ln1_b + l * DD, gln);
        // qkv: per batch (1536 x 512) @ (512 x 1024)^T -> (B, 3D, S) fp32
        gemm_hf<128, 0, true, false, false>
            <<<dim3(D3 / 128, SS / 128, BB), 256, SM128>>>(
            gln, cqkv + (size_t)l * D3 * DD, nullptr, gqkv,
            SS, D3, DD, DD, DD, (long)SS * DD, 0, (long)D3 * SS);
        // depthwise conv3 + head split + q/k normalize (fp16 out)
        conv_heads<<<dim3(SS / 64, 3 * HH, BB), 256>>>(
            gqkv, dw_w + (size_t)l * D3 * 3, gq, gk, gv);
        // scores = q k^T (K=64) -> fp32
        gemm_hf<128, 0, false, false, false>
            <<<dim3(SS / 128, SS / 128, BB * HH), 256, SM128>>>(
            gq, gk, nullptr, gsc, SS, SS, CC,
            CC, CC, (long)SS * CC, (long)SS * CC, (long)SS * SS);
        // top-k + masked softmax -> probs fp16 (in place, pitch 2*SS halves)
        topk_softmax<<<dim3(SS, BB * HH), 256>>>(gsc, temp + l * HH);
        // attn @ V -> gao fp16 in (B,S,D).  Prob rows pitch 2*SS halves!
        gemm_hf<64, 1, false, false, false>
            <<<dim3(1, SS / 128, BB * HH), 256, SM64>>>(
            (const half*)gsc, gv, nullptr, gao, SS, CC, SS,
            2 * SS, SS, (long)SS * 2 * SS, (long)CC * SS, 0);
        // proj + residual into x (fp32)
        gemm_hf<128, 0, false, false, true>
            <<<dim3(DD / 128, NBS / 128, 1), 256, SM128>>>(
            gao, cprj + (size_t)l * DD * DD, nullptr, gx,
            NBS, DD, DD, DD, DD, 0, 0, 0);
        ln_kernel<true><<<NBS, 128>>>(gx, ln2_w + l * DD, ln2_b + l * DD, gln);
        // mlp fc1 + gelu -> gmlp fp16
        gemm_hf<128, 2, false, true, false>
            <<<dim3(MLPD / 128, NBS / 128, 1), 256, SM128>>>(
            gln, cm1 + (size_t)l * MLPD * DD, mlp_b1 + l * MLPD, gmlp,
            NBS, MLPD, DD, DD, DD, 0, 0, 0);
        // mlp fc2 + bias + residual into x (fp32)
        gemm_hf<128, 0, false, false, true>
            <<<dim3(DD / 128, NBS / 128, 1), 256, SM128>>>(
            gmlp, cm2 + (size_t)l * DD * MLPD, mlp_b2 + l * DD, gx,
            NBS, DD, MLPD, MLPD, MLPD, 0, 0, 0);
    }
    ln_kernel<false><<<NBS, 128>>>(gx, lnf_w, lnf_b, out);
}

// round 16
// speedup vs baseline: 3.5929x; 1.2409x over previous
#include <cuda_runtime.h>
#include <cuda_fp16.h>
#include <cstdint>
#include <math.h>

#define BB   4
#define SS   1024
#define DD   512
#define HH   8
#define CC   64
#define MLPD 2048
#define LL   4
#define TOPKK 256
#define D3   (3*DD)

// ---------------- scratch (static device globals) ---------------------------
__device__ float g_x  [BB*SS*DD];                  // residual stream (fp32)
__device__ half  g_ln [BB*SS*DD];                  // fp16 rows (B*S, 512)
__device__ float g_qkv[(size_t)BB*D3*SS];          // (B, 3D, S) fp32
__device__ half  g_q  [BB*HH*SS*CC];               // fp16 rows (B*H*S, 64)
__device__ half  g_k  [BB*HH*SS*CC];
__device__ half  g_v  [BB*HH*CC*SS];               // fp16 transposed rows (B*H*C, 1024)
__device__ float g_sc [(size_t)BB*HH*SS*SS];       // scores fp32 -> probs fp16 (pitch 2*SS halves)
__device__ half  g_ao [BB*SS*DD];                  // fp16 rows (B*S, 512)
__device__ half  g_mlp[(size_t)BB*SS*MLPD];        // fp16 rows (B*S, 2048)
__device__ half  c_qkv[(size_t)LL*D3*DD];
__device__ half  c_prj[(size_t)LL*DD*DD];
__device__ half  c_m1 [(size_t)LL*MLPD*DD];
__device__ half  c_m2 [(size_t)LL*DD*MLPD];

// ---------------- helpers ----------------
__device__ __forceinline__ float geluf(float x) {
    return 0.5f * x * (1.0f + erff(x * 0.70710678118654752440f));
}
__device__ __forceinline__ unsigned f2key(float f) {
    unsigned u = __float_as_uint(f);
    return (u & 0x80000000u) ? ~u : (u | 0x80000000u);
}
__device__ __forceinline__ float key2f(unsigned k) {
    unsigned u = (k & 0x80000000u) ? (k & 0x7FFFFFFFu) : ~k;
    return __uint_as_float(u);
}
// fp16 mma: D(f32) += A(16x16 f16, row) * B(16x8 f16, col)
__device__ __forceinline__ void mma_hf(float c[4], const unsigned a[4],
                                       const unsigned b[2]) {
    asm volatile(
        "mma.sync.aligned.m16n8k16.row.col.f32.f16.f16.f32 "
        "{%0,%1,%2,%3}, {%4,%5,%6,%7}, {%8,%9}, {%0,%1,%2,%3};"
        : "+f"(c[0]), "+f"(c[1]), "+f"(c[2]), "+f"(c[3])
        : "r"(a[0]), "r"(a[1]), "r"(a[2]), "r"(a[3]), "r"(b[0]), "r"(b[1]));
}
__device__ __forceinline__ void cp16(unsigned saddr, const void* g) {
    asm volatile("cp.async.cg.shared.global [%0], [%1], 16;\n" :: "r"(saddr), "l"(g));
}
__device__ __forceinline__ void ldm4(unsigned addr, unsigned& r0, unsigned& r1,
                                     unsigned& r2, unsigned& r3) {
    asm volatile("ldmatrix.sync.aligned.m8n8.x4.shared.b16 {%0,%1,%2,%3}, [%4];"
                 : "=r"(r0), "=r"(r1), "=r"(r2), "=r"(r3) : "r"(addr));
}

// ---------------- weight convert: fp32 -> fp16 -------------------------------
__global__ void conv_w(const float* __restrict__ s, half* __restrict__ d, int n) {
    int i = blockIdx.x * 256 + threadIdx.x;
    if (i < n) d[i] = __float2half_rn(s[i]);
}

// ---------------- x = x_in + pos ----------------
__global__ void add_pos_kernel(const float* __restrict__ x,
                               const float* __restrict__ pos,
                               float* __restrict__ out, int total, int per_b) {
    int i = blockIdx.x * blockDim.x + threadIdx.x;
    if (i < total) out[i] = x[i] + pos[i % per_b];
}

// ---------------- layernorm over D=512 --------------------------------------
template <bool HF16OUT>
__global__ void ln_kernel(const float* __restrict__ in,
                          const float* __restrict__ w,
                          const float* __restrict__ b,
                          void* __restrict__ outv) {
    int row = blockIdx.x;
    const float* xr = in + (size_t)row * DD;
    int tid = threadIdx.x;            // 128 threads
    float v[4], s = 0.f, sq = 0.f;
#pragma unroll
    for (int i = 0; i < 4; i++) {
        v[i] = xr[tid + i * 128];
        s += v[i]; sq += v[i] * v[i];
    }
    __shared__ float rs[32], rq[32];
#pragma unroll
    for (int o = 16; o; o >>= 1) {
        s  += __shfl_down_sync(0xFFFFFFFFu, s,  o);
        sq += __shfl_down_sync(0xFFFFFFFFu, sq, o);
    }
    int warp = tid >> 5, lane = tid & 31;
    if (lane == 0) { rs[warp] = s; rq[warp] = sq; }
    __syncthreads();
    float a4 = rs[0] + rs[1] + rs[2] + rs[3];
    float c4 = rq[0] + rq[1] + rq[2] + rq[3];
    float mu   = a4 * (1.0f / DD);
    float var  = c4 * (1.0f / DD) - mu * mu;
    float rstd = rsqrtf(var + 1e-6f);
    if (HF16OUT) {
        half* yr = (half*)outv + (size_t)row * DD;
#pragma unroll
        for (int i = 0; i < 4; i++) {
            int d = tid + i * 128;
            yr[d] = __float2half_rn((v[i] - mu) * rstd * w[d] + b[d]);
        }
    } else {
        float* yr = (float*)outv + (size_t)row * DD;
#pragma unroll
        for (int i = 0; i < 4; i++) {
            int d = tid + i * 128;
            yr[d] = (v[i] - mu) * rstd * w[d] + b[d];
        }
    }
}

// =================== pipelined single-pass fp16 tensor-core GEMM =============
// C(r,q) = sum_k X(r,k)*W(q,k); X rows at X + r*ldx, W rows at W + q*ldw.
// Block tile: 128(r) x QT(q), BK=64.  8 warps of (RW x 32). fp32 accum.
// OUT_MODE: 0 = float Y (TRANS_OUT/RESID per flags)
//           1 = attn-out: fp16 into (B,S,D) rows (z = b*8+h)
//           2 = fp16 rows of width M (mlp1)
template <int QT, int OUT_MODE, bool TRANS_OUT, bool GELU_ACT, bool RESID>
__global__ void __launch_bounds__(256)
gemm_hf(const half* __restrict__ Xb, const half* __restrict__ Wb,
        const float* __restrict__ bias, void* __restrict__ Yv,
        int N, int M, int K, int ldx, int ldw, long xs, long ws, long ys) {
    constexpr int BK  = 64;
    constexpr int LDBY = 144;                // smem row stride: 128B data + 16B pad
    constexpr int XBYTES = 128 * LDBY;       // 18432
    constexpr int WBYTES = QT * LDBY;
    constexpr int STAGE  = XBYTES + WBYTES;
    constexpr int RW = (QT == 128) ? 64 : 32;
    constexpr int RTILES = RW / 16;

    extern __shared__ char smem_raw[];
    const unsigned sbase = (unsigned)__cvta_generic_to_shared(smem_raw);

    const half* X = Xb + (size_t)blockIdx.z * xs;
    const half* W = Wb + (size_t)blockIdx.z * ws;

    const int tid  = threadIdx.x;
    const int lane = tid & 31, warp = tid >> 5;
    const int wr = (QT == 128) ? (warp >> 2) : (warp >> 1);
    const int wq = (QT == 128) ? (warp & 3)  : (warp & 1);
    const int r_base = wr * RW, q_base = wq * 32;
    const int gr = lane >> 2, gc = lane & 3;
    const int lane15 = lane & 15;
    const int hi8 = (lane >> 4) & 1;

    const int q0 = blockIdx.x * QT, n0 = blockIdx.y * 128;
    const int nk = K / BK;

    const unsigned aOff = (unsigned)((r_base + lane15) * LDBY + hi8 * 16);
    const unsigned bOff = (unsigned)(XBYTES + (q_base + lane15) * LDBY + hi8 * 16);

    float acc[RTILES][4][4];
#pragma unroll
    for (int i = 0; i < RTILES; i++)
#pragma unroll
        for (int j = 0; j < 4; j++)
#pragma unroll
            for (int t = 0; t < 4; t++) acc[i][j][t] = 0.f;

    auto stage = [&](int it, int buf) {
        const int k0 = it * BK;
        const unsigned sb = sbase + buf * STAGE;
#pragma unroll
        for (int u = 0; u < 4; u++) {                 // X: 1024 16B-chunks
            int c = tid + u * 256;
            int row = c >> 3, col = c & 7;
            cp16(sb + row * LDBY + col * 16,
                 X + (size_t)(n0 + row) * ldx + k0 + col * 8);
        }
#pragma unroll
        for (int u = 0; u < QT / 32; u++) {           // W: QT*8 chunks
            int c = tid + u * 256;
            int row = c >> 3, col = c & 7;
            cp16(sb + XBYTES + row * LDBY + col * 16,
                 W + (size_t)(q0 + row) * ldw + k0 + col * 8);
        }
        asm volatile("cp.async.commit_group;\n" ::);
    };

    stage(0, 0);
    for (int it = 0; it < nk; it++) {
        if (it + 1 < nk) {
            stage(it + 1, (it + 1) & 1);
            asm volatile("cp.async.wait_group 1;\n" ::);
        } else {
            asm volatile("cp.async.wait_group 0;\n" ::);
        }
        __syncthreads();
        const unsigned sb = sbase + (it & 1) * STAGE;
        const unsigned aH0 = sb + aOff;
        const unsigned bH0 = sb + bOff;
#pragma unroll
        for (int ks = 0; ks < BK; ks += 16) {
            unsigned a[RTILES][4];
#pragma unroll
            for (int i = 0; i < RTILES; i++) {
                ldm4(aH0 + i * (16 * LDBY) + ks * 2,
                     a[i][0], a[i][1], a[i][2], a[i][3]);
            }
#pragma unroll
            for (int jp = 0; jp < 2; jp++) {
                unsigned bb[4];
                ldm4(bH0 + jp * (16 * LDBY) + ks * 2, bb[0], bb[1], bb[2], bb[3]);
#pragma unroll
                for (int jj = 0; jj < 2; jj++) {
                    const int j = 2 * jp + jj;
                    unsigned bf[2] = { bb[jj], bb[2 + jj] };
#pragma unroll
                    for (int i = 0; i < RTILES; i++) mma_hf(acc[i][j], a[i], bf);
                }
            }
        }
        __syncthreads();
    }

    // ---- epilogue ----
#pragma unroll
    for (int i = 0; i < RTILES; i++) {
#pragma unroll
        for (int j = 0; j < 4; j++) {
#pragma unroll
            for (int t = 0; t < 4; t++) {
                int r = n0 + r_base + i * 16 + gr + ((t >= 2) ? 8 : 0);
                int q = q0 + q_base + j * 8 + 2 * gc + (t & 1);
                float v = acc[i][j][t];
                if (bias) v += bias[q];
                if (GELU_ACT) v = geluf(v);
                if (OUT_MODE == 0) {
                    float* Y = (float*)Yv + (size_t)blockIdx.z * ys;
                    size_t idx = TRANS_OUT ? ((size_t)q * N + r) : ((size_t)r * M + q);
                    if (RESID) Y[idx] += v; else Y[idx] = v;
                } else if (OUT_MODE == 1) {
                    half* Y = (half*)Yv;
                    int b = blockIdx.z >> 3, h = blockIdx.z & 7;
                    Y[((size_t)(b * SS + r)) * DD + h * CC + q] = __float2half_rn(v);
                } else {
                    half* Y = (half*)Yv;
                    Y[(size_t)r * MLPD + q] = __float2half_rn(v);
                }
            }
        }
    }
}

// ------- depthwise conv3 + head split + (q,k) L2-normalize -------------------
__global__ void conv_heads(const float* __restrict__ qkv,
                           const float* __restrict__ dw,  // (3D, 3)
                           half* __restrict__ q,
                           half* __restrict__ k,
                           half* __restrict__ v) {
    int b = blockIdx.z;
    int part = blockIdx.y / HH, h = blockIdx.y % HH;
    int s0 = blockIdx.x * 64;
    int ch0 = part * DD + h * CC;
    __shared__ float tin[64][66];
    __shared__ float ct[64][65];
    int tid = threadIdx.x;

    for (int idx = tid; idx < 64 * 66; idx += 256) {
        int c = idx / 66, j = idx % 66;
        int s = s0 + j - 1;
        float val = 0.f;
        if (s >= 0 && s < SS) val = qkv[((size_t)b * D3 + ch0 + c) * SS + s];
        tin[c][j] = val;
    }
    __syncthreads();
    for (int idx = tid; idx < 4096; idx += 256) {
        int c = idx >> 6, s = idx & 63;
        const float* wp = dw + (ch0 + c) * 3;
        ct[c][s] = wp[0] * tin[c][s] + wp[1] * tin[c][s + 1] + wp[2] * tin[c][s + 2];
    }
    __syncthreads();
    if (part == 2) {
        half* outv = v + ((size_t)(b * HH + h) * CC) * SS;
        for (int idx = tid; idx < 4096; idx += 256) {
            int s = idx >> 6, c = idx & 63;
            outv[(size_t)c * SS + s0 + s] = __float2half_rn(ct[c][s]);
        }
    } else {
        __shared__ float red[4][64];
        __shared__ float rnorm[64];
        int tx = tid & 63, ty = tid >> 6;
        float p = 0.f;
        for (int c = ty * 16; c < ty * 16 + 16; c++) {
            float u = ct[c][tx];
            p += u * u;
        }
        red[ty][tx] = p;
        __syncthreads();
        if (ty == 0) {
            float nn = red[0][tx] + red[1][tx] + red[2][tx] + red[3][tx];
            rnorm[tx] = 1.f / fmaxf(sqrtf(nn), 1e-12f);
        }
        __syncthreads();
        half* out = (part == 0 ? q : k) + ((size_t)(b * HH + h) * SS + s0) * CC;
        for (int idx = tid; idx < 4096; idx += 256) {
            int s = idx >> 6, c = idx & 63;
            out[s * CC + c] = __float2half_rn(ct[c][s] * rnorm[s]);
        }
    }
}

// ------- top-k (exact radix select) + masked softmax -------------------------
// Barrier-light: warp-shuffle reductions; radix scan done entirely in warp 0.
// Reads fp32 scores row; writes probs fp16 in place (pitch 2*SS halves).
__global__ void topk_softmax(float* __restrict__ scores,
                             const float* __restrict__ temp) {
    int bh = blockIdx.y;
    int h = bh % HH;
    int s = blockIdx.x;
    float* row = scores + ((size_t)bh * SS + s) * SS;
    float t = temp[h];
    __shared__ unsigned keys[SS];
    __shared__ unsigned hist[256];
    __shared__ float fred[8];
    __shared__ unsigned sh_prefix;
    __shared__ int sh_k;
    int tid = threadIdx.x;
    int lane = tid & 31, warp = tid >> 5;

    float lmax = -3.4e38f;
#pragma unroll
    for (int i = 0; i < 4; i++) {
        int idx = tid + i * 256;
        float f = row[idx] * t;
        keys[idx] = f2key(f);
        lmax = fmaxf(lmax, f);
    }
#pragma unroll
    for (int o = 16; o; o >>= 1)
        lmax = fmaxf(lmax, __shfl_xor_sync(0xFFFFFFFFu, lmax, o));
    if (lane == 0) fred[warp] = lmax;
    hist[tid] = 0u;
    if (tid == 0) { sh_prefix = 0u; sh_k = TOPKK; }
    __syncthreads();                                    // (1)
    float maxv = fred[0];
#pragma unroll
    for (int i = 1; i < 8; i++) maxv = fmaxf(maxv, fred[i]);

    for (int pass = 0; pass < 4; pass++) {
        int shift = 24 - 8 * pass;
        unsigned pref = sh_prefix;
        unsigned mask = (pass == 0) ? 0u : (0xFFFFFFFFu << (shift + 8));
#pragma unroll
        for (int i = 0; i < 4; i++) {
            unsigned key = keys[tid + i * 256];
            if ((key & mask) == pref) atomicAdd(&hist[(key >> shift) & 255], 1u);
        }
        __syncthreads();                                // (2) hist complete
        if (warp == 0) {
            int kk = sh_k;
            unsigned hh[8];
#pragma unroll
            for (int j = 0; j < 8; j++) {
                hh[j] = hist[lane * 8 + j];
                hist[lane * 8 + j] = 0u;                // re-zero for next pass
            }
            unsigned sfx[8];                            // suffix within lane
            sfx[7] = hh[7];
#pragma unroll
            for (int j = 6; j >= 0; j--) sfx[j] = hh[j] + sfx[j + 1];
            unsigned run = sfx[0];
#pragma unroll
            for (int o = 1; o < 32; o <<= 1) {
                unsigned v = __shfl_down_sync(0xFFFFFFFFu, run, o);
                if (lane + o < 32) run += v;
            }
            unsigned above = run - sfx[0];              // sum over lanes > lane
#pragma unroll
            for (int j = 0; j < 8; j++) {
                int sfxb = (int)(above + sfx[j]);
                int nxt  = (j < 7) ? (int)(above + sfx[j + 1]) : (int)above;
                if (sfxb >= kk && nxt < kk) {
                    sh_prefix = pref | ((unsigned)(lane * 8 + j) << shift);
                    sh_k = kk - nxt;
                }
            }
        }
        __syncthreads();                                // (3) publish prefix
    }
    float vstar = key2f(sh_prefix);
    float m = fminf(fmaxf(maxv, -10000.f), 10000.f);

    float lsum = 0.f;
#pragma unroll
    for (int i = 0; i < 4; i++) {
        int idx = tid + i * 256;
        float f = key2f(keys[idx]);
        float p = (f >= vstar) ? fminf(fmaxf(f, -10000.f), 10000.f) : -10000.f;
        float e = expf(p - m);
        ((float*)keys)[idx] = e;
        lsum += e;
    }
#pragma unroll
    for (int o = 16; o; o >>= 1)
        lsum += __shfl_xor_sync(0xFFFFFFFFu, lsum, o);
    if (lane == 0) fred[warp] = lsum;
    __syncthreads();                                    // (4)
    float tsum = fred[0];
#pragma unroll
    for (int i = 1; i < 8; i++) tsum += fred[i];
    float inv = 1.f / tsum;
    half* hrow = (half*)row;
#pragma unroll
    for (int i = 0; i < 4; i++) {
        int idx = tid + i * 256;
        hrow[idx] = __float2half_rn(((float*)keys)[idx] * inv);
    }
}

// ---------------- host orchestration ----------------------------------------
extern "C" void kernel_launch(void* const* d_in, const int* in_sizes, int n_in,
                              void* d_out, int out_size) {
    (void)in_sizes; (void)n_in; (void)out_size;
    const float* x      = (const float*)d_in[0];
    const float* pos    = (const float*)d_in[1];
    const float* ln1_w  = (const float*)d_in[2];
    const float* ln1_b  = (const float*)d_in[3];
    const float* qkv_w  = (const float*)d_in[4];
    const float* dw_w   = (const float*)d_in[5];
    const float* temp   = (const float*)d_in[6];
    const float* proj_w = (const float*)d_in[7];
    const float* ln2_w  = (const float*)d_in[8];
    const float* ln2_b  = (const float*)d_in[9];
    const float* mlp_w1 = (const float*)d_in[10];
    const float* mlp_b1 = (const float*)d_in[11];
    const float* mlp_w2 = (const float*)d_in[12];
    const float* mlp_b2 = (const float*)d_in[13];
    const float* lnf_w  = (const float*)d_in[14];
    const float* lnf_b  = (const float*)d_in[15];
    float* out = (float*)d_out;

    float *gx, *gqkv, *gsc;
    half *gln, *gq, *gk, *gv, *gao, *gmlp;
    half *cqkv, *cprj, *cm1, *cm2;
    cudaGetSymbolAddress((void**)&gx,   g_x);
    cudaGetSymbolAddress((void**)&gln,  g_ln);
    cudaGetSymbolAddress((void**)&gqkv, g_qkv);
    cudaGetSymbolAddress((void**)&gq,   g_q);
    cudaGetSymbolAddress((void**)&gk,   g_k);
    cudaGetSymbolAddress((void**)&gv,   g_v);
    cudaGetSymbolAddress((void**)&gsc,  g_sc);
    cudaGetSymbolAddress((void**)&gao,  g_ao);
    cudaGetSymbolAddress((void**)&gmlp, g_mlp);
    cudaGetSymbolAddress((void**)&cqkv, c_qkv);
    cudaGetSymbolAddress((void**)&cprj, c_prj);
    cudaGetSymbolAddress((void**)&cm1,  c_m1);
    cudaGetSymbolAddress((void**)&cm2,  c_m2);

    const int SM128 = (128 * 144 + 128 * 144) * 2;   // 73728
    const int SM64  = (128 * 144 + 64 * 144) * 2;    // 55296
    cudaFuncSetAttribute(gemm_hf<128, 0, true,  false, false>,
                         cudaFuncAttributeMaxDynamicSharedMemorySize, SM128);
    cudaFuncSetAttribute(gemm_hf<128, 0, false, false, false>,
                         cudaFuncAttributeMaxDynamicSharedMemorySize, SM128);
    cudaFuncSetAttribute(gemm_hf<128, 0, false, false, true>,
                         cudaFuncAttributeMaxDynamicSharedMemorySize, SM128);
    cudaFuncSetAttribute(gemm_hf<128, 2, false, true,  false>,
                         cudaFuncAttributeMaxDynamicSharedMemorySize, SM128);
    cudaFuncSetAttribute(gemm_hf<64,  1, false, false, false>,
                         cudaFuncAttributeMaxDynamicSharedMemorySize, SM64);

    {
        int n;
        n = LL * D3 * DD;
        conv_w<<<(n + 255) / 256, 256>>>(qkv_w,  cqkv, n);
        n = LL * DD * DD;
        conv_w<<<(n + 255) / 256, 256>>>(proj_w, cprj, n);
        n = LL * MLPD * DD;
        conv_w<<<(n + 255) / 256, 256>>>(mlp_w1, cm1, n);
        n = LL * DD * MLPD;
        conv_w<<<(n + 255) / 256, 256>>>(mlp_w2, cm2, n);
    }

    const int NBS = BB * SS;
    add_pos_kernel<<<(BB * SS * DD + 255) / 256, 256>>>(x, pos, gx,
                                                        BB * SS * DD, SS * DD);

    for (int l = 0; l < LL; l++) {
        ln_kernel<true><<<NBS, 128>>>(gx, ln1_w + l * DD, ln1_b + l * DD, gln);
        // qkv: per batch (1536 x 512) @ (512 x 1024)^T -> (B, 3D, S) fp32
        gemm_hf<128, 0, true, false, false>
            <<<dim3(D3 / 128, SS / 128, BB), 256, SM128>>>(
            gln, cqkv + (size_t)l * D3 * DD, nullptr, gqkv,
            SS, D3, DD, DD, DD, (long)SS * DD, 0, (long)D3 * SS);
        // depthwise conv3 + head split + q/k normalize (fp16 out)
        conv_heads<<<dim3(SS / 64, 3 * HH, BB), 256>>>(
            gqkv, dw_w + (size_t)l * D3 * 3, gq, gk, gv);
        // scores = q k^T (K=64) -> fp32  (nk=1, single stage)
        gemm_hf<128, 0, false, false, false>
            <<<dim3(SS / 128, SS / 128, BB * HH), 256, SM128>>>(
            gq, gk, nullptr, gsc, SS, SS, CC,
            CC, CC, (long)SS * CC, (long)SS * CC, (long)SS * SS);
        // top-k + masked softmax -> probs fp16 (in place, pitch 2*SS halves)
        topk_softmax<<<dim3(SS, BB * HH), 256>>>(gsc, temp + l * HH);
        // attn @ V -> gao fp16 in (B,S,D).  Prob rows pitch 2*SS halves!
        gemm_hf<64, 1, false, false, false>
            <<<dim3(1, SS / 128, BB * HH), 256, SM64>>>(
            (const half*)gsc, gv, nullptr, gao, SS, CC, SS,
            2 * SS, SS, (long)SS * 2 * SS, (long)CC * SS, 0);
        // proj + residual into x (fp32)
        gemm_hf<128, 0, false, false, true>
            <<<dim3(DD / 128, NBS / 128, 1), 256, SM128>>>(
            gao, cprj + (size_t)l * DD * DD, nullptr, gx,
            NBS, DD, DD, DD, DD, 0, 0, 0);
        ln_kernel<true><<<NBS, 128>>>(gx, ln2_w + l * DD, ln2_b + l * DD, gln);
        // mlp fc1 + gelu -> gmlp fp16
        gemm_hf<128, 2, false, true, false>
            <<<dim3(MLPD / 128, NBS / 128, 1), 256, SM128>>>(
            gln, cm1 + (size_t)l * MLPD * DD, mlp_b1 + l * MLPD, gmlp,
            NBS, MLPD, DD, DD, DD, 0, 0, 0);
        // mlp fc2 + bias + residual into x (fp32)
        gemm_hf<128, 0, false, false, true>
            <<<dim3(DD / 128, NBS / 128, 1), 256, SM128>>>(
            gmlp, cm2 + (size_t)l * DD * MLPD, mlp_b2 + l * DD, gx,
            NBS, DD, MLPD, MLPD, MLPD, 0, 0, 0);
    }
    ln_kernel<false><<<NBS, 128>>>(gx, lnf_w, lnf_b, out);
}